// round 13
// baseline (speedup 1.0000x reference)
#include <cuda_runtime.h>
#include <cuda.h>
#include <math.h>
#include <stdint.h>

#define CCH    64
#define HWP    3136
#define NBATCH 128
#define MTOT   401408
#define CPI    49
#define NCHUNK 6272
#define GRIDG  444          // 3 CTAs/SM
#define PN     68
#define NS_TF  7
#define NS_FP  1

typedef unsigned long long u64;

__device__ float d_gpart[GRIDG * 4096];
__device__ float d_spart[GRIDG * 64];
__device__ float d_qpart[GRIDG * 64];
__device__ float d_gram[4096];
__device__ float d_sums[64];
__device__ float d_sumsq[64];
__device__ float d_wm[4096];
__device__ float d_off[64];

// ---- swizzled tile indexing (TMA SW128, box 32x64 f32, halves at 0/8KB) ----
__device__ __forceinline__ int swidx(int c, int p) {
    return ((p >> 5) << 11) + (c << 5) + ((p & 31) ^ ((c & 7) << 2));
}

// ---- helpers ---------------------------------------------------------------
__device__ __forceinline__ uint32_t fu(float x) { return __float_as_uint(x); }
__device__ __forceinline__ uint32_t tf32r(float x) {
    uint32_t r; asm("cvt.rna.tf32.f32 %0, %1;" : "=r"(r) : "f"(x)); return r;
}
__device__ __forceinline__ void mma8(float c[4], uint32_t a0, uint32_t a1,
                                     uint32_t a2, uint32_t a3,
                                     uint32_t b0, uint32_t b1) {
    asm("mma.sync.aligned.m16n8k8.row.col.f32.tf32.tf32.f32 "
        "{%0,%1,%2,%3}, {%4,%5,%6,%7}, {%8,%9}, {%0,%1,%2,%3};"
        : "+f"(c[0]), "+f"(c[1]), "+f"(c[2]), "+f"(c[3])
        : "r"(a0), "r"(a1), "r"(a2), "r"(a3), "r"(b0), "r"(b1));
}
__device__ __forceinline__ void fma2(u64 &acc, u64 a, u64 b) {
    asm("fma.rn.f32x2 %0, %1, %2, %0;" : "+l"(acc) : "l"(a), "l"(b));
}
__device__ __forceinline__ u64 dup2(float x) {
    u64 r; asm("mov.b64 %0, {%1, %1};" : "=l"(r) : "r"(__float_as_uint(x))); return r;
}
__device__ __forceinline__ float2 unpk(u64 v) {
    float2 f; asm("mov.b64 {%0, %1}, %2;" : "=f"(f.x), "=f"(f.y) : "l"(v)); return f;
}
// ---- TMA machinery ---------------------------------------------------------
__device__ __forceinline__ void mbar_init(uint32_t mb, uint32_t cnt) {
    asm volatile("mbarrier.init.shared.b64 [%0], %1;" :: "r"(mb), "r"(cnt) : "memory");
}
__device__ __forceinline__ void mbar_expect(uint32_t mb, uint32_t bytes) {
    asm volatile("mbarrier.arrive.expect_tx.shared.b64 _, [%0], %1;"
                 :: "r"(mb), "r"(bytes) : "memory");
}
__device__ __forceinline__ void mbar_wait(uint32_t mb, uint32_t parity) {
    uint32_t done;
    do {
        asm volatile("{\n\t.reg .pred p;\n\t"
                     "mbarrier.try_wait.parity.acquire.cta.shared::cta.b64 p, [%1], %2, 0x989680;\n\t"
                     "selp.b32 %0, 1, 0, p;\n\t}"
                     : "=r"(done) : "r"(mb), "r"(parity) : "memory");
    } while (!done);
}
__device__ __forceinline__ void tma_ld(uint32_t dst, const CUtensorMap* tm,
                                       int x, int y, int z, uint32_t mb) {
    asm volatile("cp.async.bulk.tensor.3d.shared::cta.global.tile.mbarrier::complete_tx::bytes "
                 "[%0], [%1, {%2, %3, %4}], [%5];"
                 :: "r"(dst), "l"(tm), "r"(x), "r"(y), "r"(z), "r"(mb) : "memory");
}
__device__ __forceinline__ void tma_st(const CUtensorMap* tm, int x, int y, int z,
                                       uint32_t src) {
    asm volatile("cp.async.bulk.tensor.3d.global.shared::cta.tile.bulk_group "
                 "[%0, {%1, %2, %3}], [%4];"
                 :: "l"(tm), "r"(x), "r"(y), "r"(z), "r"(src) : "memory");
}
__device__ __forceinline__ void tma_commit() {
    asm volatile("cp.async.bulk.commit_group;" ::: "memory");
}
template<int N> __device__ __forceinline__ void tma_wait() {
    asm volatile("cp.async.bulk.wait_group %0;" :: "n"(N) : "memory");
}
__device__ __forceinline__ void fence_async() {
    asm volatile("fence.proxy.async;" ::: "memory");
}
__device__ __forceinline__ void load_chunk(uint32_t dst, const CUtensorMap* tm,
                                           int ch, uint32_t mb) {
    int b = ch / CPI, pc = (ch - b * CPI) * 64;
    mbar_expect(mb, 16384u);
    tma_ld(dst,        tm, pc,      0, b, mb);
    tma_ld(dst + 8192, tm, pc + 32, 0, b, mb);
}

// ---------------------------------------------------------------------------
// Kernel 1: Gram via tf32 mma, TMA pipeline (3 slots, dist 2), 3 CTAs/SM.
// Sums spread over all 256 threads (no warp imbalance).
// ---------------------------------------------------------------------------
__global__ __launch_bounds__(256, 3) void gram_kernel(const __grid_constant__ CUtensorMap tmX) {
    __shared__ float raw_x[3 * 4096 + 256];
    __shared__ u64 mbar[3];
    float* xbase = (float*)(((uintptr_t)raw_x + 1023) & ~(uintptr_t)1023);

    int tid = threadIdx.x, lane = tid & 31, w = tid >> 5;
    int g = lane >> 2, t = lane & 3;
    int mb = (w & 3) * 16, nb = (w >> 2) * 32;
    int sc = tid >> 2, st = tid & 3;        // sum row / lane quarter

    uint32_t sb[3], mbr[3];
#pragma unroll
    for (int i = 0; i < 3; i++) {
        sb[i]  = (uint32_t)__cvta_generic_to_shared(xbase + i * 4096);
        mbr[i] = (uint32_t)__cvta_generic_to_shared(&mbar[i]);
    }
    if (tid == 0) { mbar_init(mbr[0], 1); mbar_init(mbr[1], 1); mbar_init(mbr[2], 1); }
    __syncthreads();

    float acc[4][4];
#pragma unroll
    for (int j = 0; j < 4; j++)
#pragma unroll
        for (int e = 0; e < 4; e++) acc[j][e] = 0.f;
    float csum = 0.f, cq = 0.f;

    if (tid == 0) {
#pragma unroll
        for (int p = 0; p < 2; p++) {
            int ch = blockIdx.x + p * GRIDG;
            if (ch < NCHUNK) load_chunk(sb[p], &tmX, ch, mbr[p]);
        }
    }

    int ph[3] = {0, 0, 0};
    int it = 0;
    for (int ch = blockIdx.x; ch < NCHUNK; ch += GRIDG, it++) {
        int s = it % 3;
        mbar_wait(mbr[s], ph[s]); ph[s] ^= 1;
        __syncthreads();

        int cn = ch + 2 * GRIDG;
        if (cn < NCHUNK && tid == 0) {
            int sn = (it + 2) % 3;
            load_chunk(sb[sn], &tmX, cn, mbr[sn]);
        }

        const float* xb = xbase + s * 4096;

        {   // exact fp32 sums / sumsq — 4 lanes per row, 4 float4 each
            float sv = 0.f, q2 = 0.f;
#pragma unroll
            for (int qq = 0; qq < 4; qq++) {
                float4 v = *(const float4*)&xb[swidx(sc, (st * 4 + qq) * 4)];
                sv += (v.x + v.y) + (v.z + v.w);
                q2 += v.x * v.x + v.y * v.y + v.z * v.z + v.w * v.w;
            }
            csum += sv; cq += q2;
        }

#pragma unroll
        for (int kg = 0; kg < 2; kg++) {
            int kb = kg * 32;
            float4 Al  = *(const float4*)&xb[swidx(mb + g,     kb + 4 * t)];
            float4 Ah  = *(const float4*)&xb[swidx(mb + g,     kb + 16 + 4 * t)];
            float4 A2l = *(const float4*)&xb[swidx(mb + g + 8, kb + 4 * t)];
            float4 A2h = *(const float4*)&xb[swidx(mb + g + 8, kb + 16 + 4 * t)];
#pragma unroll
            for (int j = 0; j < 4; j++) {
                float4 Bl = *(const float4*)&xb[swidx(nb + 8 * j + g, kb + 4 * t)];
                float4 Bh = *(const float4*)&xb[swidx(nb + 8 * j + g, kb + 16 + 4 * t)];
                mma8(acc[j], fu(Al.x), fu(A2l.x), fu(Ah.x), fu(A2h.x), fu(Bl.x), fu(Bh.x));
                mma8(acc[j], fu(Al.y), fu(A2l.y), fu(Ah.y), fu(A2h.y), fu(Bl.y), fu(Bh.y));
                mma8(acc[j], fu(Al.z), fu(A2l.z), fu(Ah.z), fu(A2h.z), fu(Bl.z), fu(Bh.z));
                mma8(acc[j], fu(Al.w), fu(A2l.w), fu(Ah.w), fu(A2h.w), fu(Bl.w), fu(Bh.w));
            }
        }
    }

    float* gp = &d_gpart[blockIdx.x * 4096];
#pragma unroll
    for (int j = 0; j < 4; j++) {
        int col = nb + 8 * j + 2 * t;
        gp[(mb + g)     * 64 + col]     = acc[j][0];
        gp[(mb + g)     * 64 + col + 1] = acc[j][1];
        gp[(mb + g + 8) * 64 + col]     = acc[j][2];
        gp[(mb + g + 8) * 64 + col + 1] = acc[j][3];
    }
    // reduce 4 lane-partials per row
    csum += __shfl_xor_sync(0xffffffffu, csum, 1);
    csum += __shfl_xor_sync(0xffffffffu, csum, 2);
    cq   += __shfl_xor_sync(0xffffffffu, cq, 1);
    cq   += __shfl_xor_sync(0xffffffffu, cq, 2);
    if (st == 0) {
        d_spart[blockIdx.x * 64 + sc] = csum;
        d_qpart[blockIdx.x * 64 + sc] = cq;
    }
}

// ---------------------------------------------------------------------------
// Kernel 1b: reduce per-CTA partials.
// ---------------------------------------------------------------------------
__global__ __launch_bounds__(128) void reduce_kernel() {
    int idx = blockIdx.x * 128 + threadIdx.x;
    if (idx < 4096) {
        float s = 0.f;
#pragma unroll 4
        for (int c = 0; c < GRIDG; c++) s += d_gpart[c * 4096 + idx];
        d_gram[idx] = s;
    } else if (idx < 4160) {
        int j = idx - 4096;
        float s = 0.f;
#pragma unroll 4
        for (int c = 0; c < GRIDG; c++) s += d_spart[c * 64 + j];
        d_sums[j] = s;
    } else if (idx < 4224) {
        int j = idx - 4160;
        float s = 0.f;
#pragma unroll 4
        for (int c = 0; c < GRIDG; c++) s += d_qpart[c * 64 + j];
        d_sumsq[j] = s;
    }
}

// ---------------------------------------------------------------------------
// Kernel 2: Sigma + Newton-Schulz. 512 threads, 2-stage iterations (as R12).
// ---------------------------------------------------------------------------
__device__ __forceinline__ void mm_tf16(const float* __restrict__ A,
                                        const float* __restrict__ Bm,
                                        int g, int t, int mb, int nb,
                                        float acc[2][4]) {
#pragma unroll
    for (int j = 0; j < 2; j++)
#pragma unroll
        for (int e = 0; e < 4; e++) acc[j][e] = 0.f;
#pragma unroll
    for (int ks = 0; ks < 8; ks++) {
        uint32_t a0 = fu(A[(mb + g)     * PN + 8 * ks + t]);
        uint32_t a1 = fu(A[(mb + g + 8) * PN + 8 * ks + t]);
        uint32_t a2 = fu(A[(mb + g)     * PN + 8 * ks + t + 4]);
        uint32_t a3 = fu(A[(mb + g + 8) * PN + 8 * ks + t + 4]);
#pragma unroll
        for (int j = 0; j < 2; j++) {
            uint32_t b0 = fu(Bm[(8 * ks + t)     * PN + nb + 8 * j + g]);
            uint32_t b1 = fu(Bm[(8 * ks + t + 4) * PN + nb + 8 * j + g]);
            mma8(acc[j], a0, a1, a2, a3, b0, b1);
        }
    }
}

__device__ __forceinline__ void st_tf16(float* __restrict__ D, int g, int t,
                                        int mb, int nb, const float acc[2][4]) {
#pragma unroll
    for (int j = 0; j < 2; j++) {
        int c0 = nb + 8 * j + 2 * t;
        *(float2*)&D[(mb + g)     * PN + c0] = make_float2(acc[j][0], acc[j][1]);
        *(float2*)&D[(mb + g + 8) * PN + c0] = make_float2(acc[j][2], acc[j][3]);
    }
}

__device__ __forceinline__ void mm_sym2(const float* __restrict__ A,
                                        const float* __restrict__ Bm,
                                        int ib, int jb, u64 acc[2][2]) {
#pragma unroll
    for (int ii = 0; ii < 2; ii++) { acc[ii][0] = 0ull; acc[ii][1] = 0ull; }
#pragma unroll 8
    for (int k = 0; k < 64; k++) {
        float2 a = *(const float2*)&A[k * PN + ib];
        ulonglong2 bv = *(const ulonglong2*)&Bm[k * PN + jb];
        u64 d0 = dup2(a.x), d1 = dup2(a.y);
        fma2(acc[0][0], d0, bv.x); fma2(acc[0][1], d0, bv.y);
        fma2(acc[1][0], d1, bv.x); fma2(acc[1][1], d1, bv.y);
    }
}

__global__ __launch_bounds__(512) void ns_kernel(const float* __restrict__ beta) {
    __shared__ __align__(16) float B0[64 * PN];
    __shared__ __align__(16) float B1[64 * PN];
    __shared__ __align__(16) float B2[64 * PN];
    __shared__ __align__(16) float B3[64 * PN];
    int tid = threadIdx.x, lane = tid & 31, w = tid >> 5;
    int g = lane >> 2, t = lane & 3;
    int mb = (w & 3) * 16, nb = (w >> 2) * 16;
    int ib = (tid >> 4) * 2, jb = (tid & 15) * 4;
    const float inv_m = 1.f / (float)MTOT;

    for (int idx = tid; idx < 4096; idx += 512) {
        int i = idx >> 6, j = idx & 63;
        float mi = d_sums[i] * inv_m, mj = d_sums[j] * inv_m;
        float s;
        if (i == j) s = d_sumsq[i] * inv_m - mi * mi + 1e-5f;
        else        s = (d_gram[idx] * inv_m - mi * mj) * 0.9f;
        B1[i * PN + j] = s;
    }
    __syncthreads();

    if (tid < 32) {
        float s = B1[tid * PN + tid] + B1[(tid + 32) * PN + (tid + 32)];
#pragma unroll
        for (int o = 16; o > 0; o >>= 1) s += __shfl_xor_sync(0xffffffffu, s, o);
        if (tid == 0) B2[0] = s;
    }
    __syncthreads();
    float rTr = 1.f / B2[0];
    float srt = sqrtf(rTr);
    __syncthreads();

    for (int idx = tid; idx < 4096; idx += 512) {
        int i = idx >> 6, j = idx & 63;
        float sn = B1[i * PN + j] * rTr;
        B1[i * PN + j] = sn;
        B0[i * PN + j] = (i == j ? 1.5f : 0.f) - 0.5f * sn;
    }
    __syncthreads();

    float a4[2][4], b4[2][4];
    for (int it = 0; it < NS_TF; it++) {
        mm_tf16(B0, B0, g, t, mb, nb, a4);
        mm_tf16(B0, B1, g, t, mb, nb, b4);
        st_tf16(B2, g, t, mb, nb, a4);
        st_tf16(B3, g, t, mb, nb, b4);
        __syncthreads();
        mm_tf16(B2, B3, g, t, mb, nb, a4);
#pragma unroll
        for (int j = 0; j < 2; j++) {
            int c0 = nb + 8 * j + 2 * t;
            float2 p0 = *(const float2*)&B0[(mb + g)     * PN + c0];
            float2 p1 = *(const float2*)&B0[(mb + g + 8) * PN + c0];
            *(float2*)&B0[(mb + g)     * PN + c0] =
                make_float2(1.5f * p0.x - 0.5f * a4[j][0], 1.5f * p0.y - 0.5f * a4[j][1]);
            *(float2*)&B0[(mb + g + 8) * PN + c0] =
                make_float2(1.5f * p1.x - 0.5f * a4[j][2], 1.5f * p1.y - 0.5f * a4[j][3]);
        }
        __syncthreads();
    }

    u64 acc[2][2], acc2[2][2];
    for (int it = 0; it < NS_FP; it++) {
        mm_sym2(B0, B0, ib, jb, acc);
        mm_sym2(B0, B1, ib, jb, acc2);
#pragma unroll
        for (int ii = 0; ii < 2; ii++) {
            float2 l0 = unpk(acc[ii][0]);
            float2 l1 = unpk(acc[ii][1]);
            *(float4*)&B2[(ib + ii) * PN + jb] = make_float4(l0.x, l0.y, l1.x, l1.y);
            float2 m0 = unpk(acc2[ii][0]);
            float2 m1 = unpk(acc2[ii][1]);
            *(float4*)&B3[(ib + ii) * PN + jb] = make_float4(m0.x, m0.y, m1.x, m1.y);
        }
        __syncthreads();
        mm_sym2(B2, B3, ib, jb, acc);
#pragma unroll
        for (int ii = 0; ii < 2; ii++) {
            float2 l0 = unpk(acc[ii][0]);
            float2 l1 = unpk(acc[ii][1]);
            int base = (ib + ii) * PN + jb;
            float4 p = *(const float4*)&B0[base];
            *(float4*)&B0[base] = make_float4(1.5f * p.x - 0.5f * l0.x,
                                              1.5f * p.y - 0.5f * l0.y,
                                              1.5f * p.z - 0.5f * l1.x,
                                              1.5f * p.w - 0.5f * l1.y);
        }
        __syncthreads();
    }

#pragma unroll
    for (int ii = 0; ii < 2; ii++) {
        float4 p = *(const float4*)&B0[(ib + ii) * PN + jb];
        *(float4*)&d_wm[(ib + ii) * 64 + jb] =
            make_float4(p.x * srt, p.y * srt, p.z * srt, p.w * srt);
    }
    if (tid < 64) {
        float s = 0.f;
#pragma unroll 8
        for (int j = 0; j < 64; j++) s += B0[tid * PN + j] * (d_sums[j] * inv_m);
        d_off[tid] = beta[tid] - srt * s;
    }
}

// ---------------------------------------------------------------------------
// Kernel 3: out = x + E@x + off. 3 CTAs/SM: 2 x-slots + 2 y-slots, 16x32 warp
// tiles (half the A-frag registers), prefetch distance 1.
// ---------------------------------------------------------------------------
__global__ __launch_bounds__(256, 3) void apply_kernel(
        const __grid_constant__ CUtensorMap tmX,
        const __grid_constant__ CUtensorMap tmO) {
    __shared__ float raw[4 * 4096 + 256];
    __shared__ float osh[64];
    __shared__ u64 mbar[2];
    float* xbase = (float*)(((uintptr_t)raw + 1023) & ~(uintptr_t)1023);
    float* ybase = xbase + 2 * 4096;

    int tid = threadIdx.x, lane = tid & 31, w = tid >> 5;
    int g = lane >> 2, t = lane & 3;
    int mb = (w & 3) * 16;       // 4 row groups of 16
    int nb = (w >> 2) * 32;      // 2 col groups of 32
    int r0 = mb + g, r1 = r0 + 8;

    uint32_t sb[2], mbr[2], yb[2];
#pragma unroll
    for (int i = 0; i < 2; i++) {
        sb[i]  = (uint32_t)__cvta_generic_to_shared(xbase + i * 4096);
        mbr[i] = (uint32_t)__cvta_generic_to_shared(&mbar[i]);
        yb[i]  = (uint32_t)__cvta_generic_to_shared(ybase + i * 4096);
    }
    if (tid == 0) { mbar_init(mbr[0], 1); mbar_init(mbr[1], 1); }

    // resident E = wm - I fragments (16 rows per warp -> 32 regs)
    uint32_t ea[8][4];
#pragma unroll
    for (int ks = 0; ks < 8; ks++) {
        int c0 = 8 * ks + t, c1 = c0 + 4;
        ea[ks][0] = tf32r(d_wm[r0 * 64 + c0] - (r0 == c0 ? 1.f : 0.f));
        ea[ks][1] = tf32r(d_wm[r1 * 64 + c0] - (r1 == c0 ? 1.f : 0.f));
        ea[ks][2] = tf32r(d_wm[r0 * 64 + c1] - (r0 == c1 ? 1.f : 0.f));
        ea[ks][3] = tf32r(d_wm[r1 * 64 + c1] - (r1 == c1 ? 1.f : 0.f));
    }
    if (tid < 64) osh[tid] = d_off[tid];
    __syncthreads();
    float o0 = osh[r0], o1 = osh[r1];

    if (tid == 0 && blockIdx.x < NCHUNK)
        load_chunk(sb[0], &tmX, blockIdx.x, mbr[0]);

    int ph[2] = {0, 0};
    int it = 0;
    for (int ch = blockIdx.x; ch < NCHUNK; ch += GRIDG, it++) {
        int s = it & 1;
        if (tid == 0) tma_wait<1>();          // y[it&1] store (epoch it-2) done
        mbar_wait(mbr[s], ph[s]); ph[s] ^= 1;
        __syncthreads();

        int cn = ch + GRIDG;
        if (cn < NCHUNK && tid == 0)
            load_chunk(sb[s ^ 1], &tmX, cn, mbr[s ^ 1]);

        const float* xb = xbase + s * 4096;
        float* yw = ybase + (it & 1) * 4096;

        // C-init: acc = x(frag) + off
        float acc[4][4];
#pragma unroll
        for (int j = 0; j < 4; j++) {
            int cc = nb + 8 * j + 2 * t;
            float2 v0 = *(const float2*)&xb[swidx(r0, cc)];
            float2 v1 = *(const float2*)&xb[swidx(r1, cc)];
            acc[j][0] = o0 + v0.x; acc[j][1] = o0 + v0.y;
            acc[j][2] = o1 + v1.x; acc[j][3] = o1 + v1.y;
        }

#pragma unroll
        for (int ks = 0; ks < 8; ks++) {
#pragma unroll
            for (int j = 0; j < 4; j++) {
                uint32_t b0 = fu(xb[swidx(8 * ks + t,     nb + 8 * j + g)]);
                uint32_t b1 = fu(xb[swidx(8 * ks + t + 4, nb + 8 * j + g)]);
                mma8(acc[j], ea[ks][0], ea[ks][1], ea[ks][2], ea[ks][3], b0, b1);
            }
        }

#pragma unroll
        for (int j = 0; j < 4; j++) {
            int cc = nb + 8 * j + 2 * t;
            *(float2*)&yw[swidx(r0, cc)] = make_float2(acc[j][0], acc[j][1]);
            *(float2*)&yw[swidx(r1, cc)] = make_float2(acc[j][2], acc[j][3]);
        }
        __syncthreads();

        if (tid == 0) {
            fence_async();
            int b = ch / CPI, pc = (ch - b * CPI) * 64;
            uint32_t ys = yb[it & 1];
            tma_st(&tmO, pc,      0, b, ys);
            tma_st(&tmO, pc + 32, 0, b, ys + 8192);
            tma_commit();
        }
    }
    if (tid == 0) tma_wait<0>();
}

// ---------------------------------------------------------------------------
typedef CUresult (CUDAAPI *PFN_tmEnc)(CUtensorMap*, CUtensorMapDataType, cuuint32_t,
                                      void*, const cuuint64_t*, const cuuint64_t*,
                                      const cuuint32_t*, const cuuint32_t*,
                                      CUtensorMapInterleave, CUtensorMapSwizzle,
                                      CUtensorMapL2promotion, CUtensorMapFloatOOBfill);

extern "C" void kernel_launch(void* const* d_in, const int* in_sizes, int n_in,
                              void* d_out, int out_size) {
    (void)in_sizes; (void)n_in; (void)out_size;
    const float* X    = (const float*)d_in[0];
    const float* beta = (const float*)d_in[1];
    float* out        = (float*)d_out;

    PFN_tmEnc enc = nullptr;
    cudaDriverEntryPointQueryResult qr;
    cudaGetDriverEntryPoint("cuTensorMapEncodeTiled", (void**)&enc,
                            cudaEnableDefault, &qr);

    CUtensorMap tmX, tmO;
    cuuint64_t dims[3]    = {(cuuint64_t)HWP, (cuuint64_t)CCH, (cuuint64_t)NBATCH};
    cuuint64_t strides[2] = {(cuuint64_t)HWP * 4ull,
                             (cuuint64_t)CCH * (cuuint64_t)HWP * 4ull};
    cuuint32_t box[3] = {32u, 64u, 1u};
    cuuint32_t es[3]  = {1u, 1u, 1u};
    enc(&tmX, CU_TENSOR_MAP_DATA_TYPE_FLOAT32, 3, (void*)X, dims, strides, box, es,
        CU_TENSOR_MAP_INTERLEAVE_NONE, CU_TENSOR_MAP_SWIZZLE_128B,
        CU_TENSOR_MAP_L2_PROMOTION_L2_128B, CU_TENSOR_MAP_FLOAT_OOB_FILL_NONE);
    enc(&tmO, CU_TENSOR_MAP_DATA_TYPE_FLOAT32, 3, (void*)out, dims, strides, box, es,
        CU_TENSOR_MAP_INTERLEAVE_NONE, CU_TENSOR_MAP_SWIZZLE_128B,
        CU_TENSOR_MAP_L2_PROMOTION_L2_128B, CU_TENSOR_MAP_FLOAT_OOB_FILL_NONE);

    gram_kernel<<<GRIDG, 256>>>(tmX);
    reduce_kernel<<<33, 128>>>();
    ns_kernel<<<1, 512>>>(beta);
    apply_kernel<<<GRIDG, 256>>>(tmX, tmO);
}

// round 14
// speedup vs baseline: 1.3050x; 1.3050x over previous
#include <cuda_runtime.h>
#include <cuda.h>
#include <math.h>
#include <stdint.h>

#define CCH    64
#define HWP    3136
#define NBATCH 128
#define MTOT   401408
#define CPI    49
#define NCHUNK 6272
#define GRIDB  296
#define PN     68
#define NS_TF  7
#define NS_FP  1
#define RGRP   8            // reduce groups
#define RCPG   37           // CTAs per reduce group (8*37=296)

typedef unsigned long long u64;

__device__ float d_gpart[GRIDB * 4096];
__device__ float d_spart[GRIDB * 64];
__device__ float d_qpart[GRIDB * 64];
__device__ float d_gram[4096];
__device__ float d_sums[64];
__device__ float d_sumsq[64];
__device__ float d_wm[4096];
__device__ float d_off[64];

// ---- swizzled tile indexing (TMA SW128, box 32x64 f32, halves at 0/8KB) ----
__device__ __forceinline__ int swidx(int c, int p) {
    return ((p >> 5) << 11) + (c << 5) + ((p & 31) ^ ((c & 7) << 2));
}

// ---- helpers ---------------------------------------------------------------
__device__ __forceinline__ uint32_t fu(float x) { return __float_as_uint(x); }
__device__ __forceinline__ uint32_t tf32r(float x) {
    uint32_t r; asm("cvt.rna.tf32.f32 %0, %1;" : "=r"(r) : "f"(x)); return r;
}
__device__ __forceinline__ void mma8(float c[4], uint32_t a0, uint32_t a1,
                                     uint32_t a2, uint32_t a3,
                                     uint32_t b0, uint32_t b1) {
    asm("mma.sync.aligned.m16n8k8.row.col.f32.tf32.tf32.f32 "
        "{%0,%1,%2,%3}, {%4,%5,%6,%7}, {%8,%9}, {%0,%1,%2,%3};"
        : "+f"(c[0]), "+f"(c[1]), "+f"(c[2]), "+f"(c[3])
        : "r"(a0), "r"(a1), "r"(a2), "r"(a3), "r"(b0), "r"(b1));
}
__device__ __forceinline__ void fma2(u64 &acc, u64 a, u64 b) {
    asm("fma.rn.f32x2 %0, %1, %2, %0;" : "+l"(acc) : "l"(a), "l"(b));
}
__device__ __forceinline__ u64 dup2(float x) {
    u64 r; asm("mov.b64 %0, {%1, %1};" : "=l"(r) : "r"(__float_as_uint(x))); return r;
}
__device__ __forceinline__ float2 unpk(u64 v) {
    float2 f; asm("mov.b64 {%0, %1}, %2;" : "=f"(f.x), "=f"(f.y) : "l"(v)); return f;
}
// ---- TMA machinery ---------------------------------------------------------
__device__ __forceinline__ void mbar_init(uint32_t mb, uint32_t cnt) {
    asm volatile("mbarrier.init.shared.b64 [%0], %1;" :: "r"(mb), "r"(cnt) : "memory");
}
__device__ __forceinline__ void mbar_expect(uint32_t mb, uint32_t bytes) {
    asm volatile("mbarrier.arrive.expect_tx.shared.b64 _, [%0], %1;"
                 :: "r"(mb), "r"(bytes) : "memory");
}
__device__ __forceinline__ void mbar_wait(uint32_t mb, uint32_t parity) {
    uint32_t done;
    do {
        asm volatile("{\n\t.reg .pred p;\n\t"
                     "mbarrier.try_wait.parity.acquire.cta.shared::cta.b64 p, [%1], %2, 0x989680;\n\t"
                     "selp.b32 %0, 1, 0, p;\n\t}"
                     : "=r"(done) : "r"(mb), "r"(parity) : "memory");
    } while (!done);
}
__device__ __forceinline__ void tma_ld(uint32_t dst, const CUtensorMap* tm,
                                       int x, int y, int z, uint32_t mb) {
    asm volatile("cp.async.bulk.tensor.3d.shared::cta.global.tile.mbarrier::complete_tx::bytes "
                 "[%0], [%1, {%2, %3, %4}], [%5];"
                 :: "r"(dst), "l"(tm), "r"(x), "r"(y), "r"(z), "r"(mb) : "memory");
}
__device__ __forceinline__ void tma_st(const CUtensorMap* tm, int x, int y, int z,
                                       uint32_t src) {
    asm volatile("cp.async.bulk.tensor.3d.global.shared::cta.tile.bulk_group "
                 "[%0, {%1, %2, %3}], [%4];"
                 :: "l"(tm), "r"(x), "r"(y), "r"(z), "r"(src) : "memory");
}
__device__ __forceinline__ void tma_commit() {
    asm volatile("cp.async.bulk.commit_group;" ::: "memory");
}
template<int N> __device__ __forceinline__ void tma_wait() {
    asm volatile("cp.async.bulk.wait_group %0;" :: "n"(N) : "memory");
}
__device__ __forceinline__ void fence_async() {
    asm volatile("fence.proxy.async;" ::: "memory");
}
__device__ __forceinline__ void load_chunk(uint32_t dst, const CUtensorMap* tm,
                                           int ch, uint32_t mb) {
    int b = ch / CPI, pc = (ch - b * CPI) * 64;
    mbar_expect(mb, 16384u);
    tma_ld(dst,        tm, pc,      0, b, mb);
    tma_ld(dst + 8192, tm, pc + 32, 0, b, mb);
}

__global__ void zero_scratch() {
    int i = blockIdx.x * 256 + threadIdx.x;
    if (i < 4096) d_gram[i] = 0.f;
    if (i < 64)   { d_sums[i] = 0.f; d_sumsq[i] = 0.f; }
}

// ---------------------------------------------------------------------------
// Kernel 1: Gram via tf32 mma, TMA-loaded chunks. Sums spread over 256 thr.
// ---------------------------------------------------------------------------
__global__ __launch_bounds__(256, 2) void gram_kernel(const __grid_constant__ CUtensorMap tmX) {
    __shared__ float raw_x[3 * 4096 + 256];
    __shared__ u64 mbar[3];
    float* xbase = (float*)(((uintptr_t)raw_x + 1023) & ~(uintptr_t)1023);

    int tid = threadIdx.x, lane = tid & 31, w = tid >> 5;
    int g = lane >> 2, t = lane & 3;
    int mb = (w & 3) * 16, nb = (w >> 2) * 32;
    int sc = tid >> 2, st = tid & 3;       // channel-sum row / lane-quarter

    uint32_t sb[3], mbr[3];
#pragma unroll
    for (int i = 0; i < 3; i++) {
        sb[i]  = (uint32_t)__cvta_generic_to_shared(xbase + i * 4096);
        mbr[i] = (uint32_t)__cvta_generic_to_shared(&mbar[i]);
    }
    if (tid == 0) { mbar_init(mbr[0], 1); mbar_init(mbr[1], 1); mbar_init(mbr[2], 1); }
    __syncthreads();

    float acc[4][4];
#pragma unroll
    for (int j = 0; j < 4; j++)
#pragma unroll
        for (int e = 0; e < 4; e++) acc[j][e] = 0.f;
    float csum = 0.f, cq = 0.f;

    if (tid == 0) {
#pragma unroll
        for (int p = 0; p < 2; p++)
            load_chunk(sb[p], &tmX, blockIdx.x + p * GRIDB, mbr[p]);
    }

    int ph[3] = {0, 0, 0};
    int it = 0;
    for (int ch = blockIdx.x; ch < NCHUNK; ch += GRIDB, it++) {
        int s = it % 3;
        mbar_wait(mbr[s], ph[s]); ph[s] ^= 1;
        __syncthreads();

        int cn = ch + 2 * GRIDB;
        if (cn < NCHUNK && tid == 0) {
            int sn = (it + 2) % 3;
            load_chunk(sb[sn], &tmX, cn, mbr[sn]);
        }

        const float* xb = xbase + s * 4096;

        {   // exact fp32 sums / sumsq — all 256 threads, 4 float4 each
            float sv = 0.f, q2 = 0.f;
#pragma unroll
            for (int qq = 0; qq < 4; qq++) {
                float4 v = *(const float4*)&xb[swidx(sc, (st * 4 + qq) * 4)];
                sv += (v.x + v.y) + (v.z + v.w);
                q2 += v.x * v.x + v.y * v.y + v.z * v.z + v.w * v.w;
            }
            csum += sv; cq += q2;
        }

#pragma unroll
        for (int kg = 0; kg < 2; kg++) {
            int kb = kg * 32;
            float4 Al  = *(const float4*)&xb[swidx(mb + g,     kb + 4 * t)];
            float4 Ah  = *(const float4*)&xb[swidx(mb + g,     kb + 16 + 4 * t)];
            float4 A2l = *(const float4*)&xb[swidx(mb + g + 8, kb + 4 * t)];
            float4 A2h = *(const float4*)&xb[swidx(mb + g + 8, kb + 16 + 4 * t)];
#pragma unroll
            for (int j = 0; j < 4; j++) {
                float4 Bl = *(const float4*)&xb[swidx(nb + 8 * j + g, kb + 4 * t)];
                float4 Bh = *(const float4*)&xb[swidx(nb + 8 * j + g, kb + 16 + 4 * t)];
                mma8(acc[j], fu(Al.x), fu(A2l.x), fu(Ah.x), fu(A2h.x), fu(Bl.x), fu(Bh.x));
                mma8(acc[j], fu(Al.y), fu(A2l.y), fu(Ah.y), fu(A2h.y), fu(Bl.y), fu(Bh.y));
                mma8(acc[j], fu(Al.z), fu(A2l.z), fu(Ah.z), fu(A2h.z), fu(Bl.z), fu(Bh.z));
                mma8(acc[j], fu(Al.w), fu(A2l.w), fu(Ah.w), fu(A2h.w), fu(Bl.w), fu(Bh.w));
            }
        }
    }

    float* gp = &d_gpart[blockIdx.x * 4096];
#pragma unroll
    for (int j = 0; j < 4; j++) {
        int col = nb + 8 * j + 2 * t;
        gp[(mb + g)     * 64 + col]     = acc[j][0];
        gp[(mb + g)     * 64 + col + 1] = acc[j][1];
        gp[(mb + g + 8) * 64 + col]     = acc[j][2];
        gp[(mb + g + 8) * 64 + col + 1] = acc[j][3];
    }
    csum += __shfl_xor_sync(0xffffffffu, csum, 1);
    csum += __shfl_xor_sync(0xffffffffu, csum, 2);
    cq   += __shfl_xor_sync(0xffffffffu, cq, 1);
    cq   += __shfl_xor_sync(0xffffffffu, cq, 2);
    if (st == 0) {
        d_spart[blockIdx.x * 64 + sc] = csum;
        d_qpart[blockIdx.x * 64 + sc] = cq;
    }
}

// ---------------------------------------------------------------------------
// Kernel 1b: hierarchical reduce — 8 groups x 37 CTAs, 8-way atomics.
// ---------------------------------------------------------------------------
__global__ __launch_bounds__(128) void reduce_kernel() {
    int grp = blockIdx.x / 33;              // 0..7
    int blk = blockIdx.x - grp * 33;        // 0..32
    int idx = blk * 128 + threadIdx.x;
    int c0 = grp * RCPG;
    if (idx < 4096) {
        float s = 0.f;
#pragma unroll 4
        for (int c = 0; c < RCPG; c++) s += d_gpart[(c0 + c) * 4096 + idx];
        atomicAdd(&d_gram[idx], s);
    } else if (idx < 4160) {
        int j = idx - 4096;
        float s = 0.f;
#pragma unroll 4
        for (int c = 0; c < RCPG; c++) s += d_spart[(c0 + c) * 64 + j];
        atomicAdd(&d_sums[j], s);
    } else if (idx < 4224) {
        int j = idx - 4160;
        float s = 0.f;
#pragma unroll 4
        for (int c = 0; c < RCPG; c++) s += d_qpart[(c0 + c) * 64 + j];
        atomicAdd(&d_sumsq[j], s);
    }
}

// ---------------------------------------------------------------------------
// Kernel 2: Sigma + Newton-Schulz. 512 threads, 2-stage iterations.
// ---------------------------------------------------------------------------
__device__ __forceinline__ void mm_tf16(const float* __restrict__ A,
                                        const float* __restrict__ Bm,
                                        int g, int t, int mb, int nb,
                                        float acc[2][4]) {
#pragma unroll
    for (int j = 0; j < 2; j++)
#pragma unroll
        for (int e = 0; e < 4; e++) acc[j][e] = 0.f;
#pragma unroll
    for (int ks = 0; ks < 8; ks++) {
        uint32_t a0 = fu(A[(mb + g)     * PN + 8 * ks + t]);
        uint32_t a1 = fu(A[(mb + g + 8) * PN + 8 * ks + t]);
        uint32_t a2 = fu(A[(mb + g)     * PN + 8 * ks + t + 4]);
        uint32_t a3 = fu(A[(mb + g + 8) * PN + 8 * ks + t + 4]);
#pragma unroll
        for (int j = 0; j < 2; j++) {
            uint32_t b0 = fu(Bm[(8 * ks + t)     * PN + nb + 8 * j + g]);
            uint32_t b1 = fu(Bm[(8 * ks + t + 4) * PN + nb + 8 * j + g]);
            mma8(acc[j], a0, a1, a2, a3, b0, b1);
        }
    }
}

__device__ __forceinline__ void st_tf16(float* __restrict__ D, int g, int t,
                                        int mb, int nb, const float acc[2][4]) {
#pragma unroll
    for (int j = 0; j < 2; j++) {
        int c0 = nb + 8 * j + 2 * t;
        *(float2*)&D[(mb + g)     * PN + c0] = make_float2(acc[j][0], acc[j][1]);
        *(float2*)&D[(mb + g + 8) * PN + c0] = make_float2(acc[j][2], acc[j][3]);
    }
}

__device__ __forceinline__ void mm_sym2(const float* __restrict__ A,
                                        const float* __restrict__ Bm,
                                        int ib, int jb, u64 acc[2][2]) {
#pragma unroll
    for (int ii = 0; ii < 2; ii++) { acc[ii][0] = 0ull; acc[ii][1] = 0ull; }
#pragma unroll 8
    for (int k = 0; k < 64; k++) {
        float2 a = *(const float2*)&A[k * PN + ib];
        ulonglong2 bv = *(const ulonglong2*)&Bm[k * PN + jb];
        u64 d0 = dup2(a.x), d1 = dup2(a.y);
        fma2(acc[0][0], d0, bv.x); fma2(acc[0][1], d0, bv.y);
        fma2(acc[1][0], d1, bv.x); fma2(acc[1][1], d1, bv.y);
    }
}

__global__ __launch_bounds__(512) void ns_kernel(const float* __restrict__ beta) {
    __shared__ __align__(16) float B0[64 * PN];
    __shared__ __align__(16) float B1[64 * PN];
    __shared__ __align__(16) float B2[64 * PN];
    __shared__ __align__(16) float B3[64 * PN];
    int tid = threadIdx.x, lane = tid & 31, w = tid >> 5;
    int g = lane >> 2, t = lane & 3;
    int mb = (w & 3) * 16, nb = (w >> 2) * 16;
    int ib = (tid >> 4) * 2, jb = (tid & 15) * 4;
    const float inv_m = 1.f / (float)MTOT;

    for (int idx = tid; idx < 4096; idx += 512) {
        int i = idx >> 6, j = idx & 63;
        float mi = d_sums[i] * inv_m, mj = d_sums[j] * inv_m;
        float s;
        if (i == j) s = d_sumsq[i] * inv_m - mi * mi + 1e-5f;
        else        s = (d_gram[idx] * inv_m - mi * mj) * 0.9f;
        B1[i * PN + j] = s;
    }
    __syncthreads();

    if (tid < 32) {
        float s = B1[tid * PN + tid] + B1[(tid + 32) * PN + (tid + 32)];
#pragma unroll
        for (int o = 16; o > 0; o >>= 1) s += __shfl_xor_sync(0xffffffffu, s, o);
        if (tid == 0) B2[0] = s;
    }
    __syncthreads();
    float rTr = 1.f / B2[0];
    float srt = sqrtf(rTr);
    __syncthreads();

    for (int idx = tid; idx < 4096; idx += 512) {
        int i = idx >> 6, j = idx & 63;
        float sn = B1[i * PN + j] * rTr;
        B1[i * PN + j] = sn;
        B0[i * PN + j] = (i == j ? 1.5f : 0.f) - 0.5f * sn;
    }
    __syncthreads();

    float a4[2][4], b4[2][4];
    for (int it = 0; it < NS_TF; it++) {
        mm_tf16(B0, B0, g, t, mb, nb, a4);
        mm_tf16(B0, B1, g, t, mb, nb, b4);
        st_tf16(B2, g, t, mb, nb, a4);
        st_tf16(B3, g, t, mb, nb, b4);
        __syncthreads();
        mm_tf16(B2, B3, g, t, mb, nb, a4);
#pragma unroll
        for (int j = 0; j < 2; j++) {
            int c0 = nb + 8 * j + 2 * t;
            float2 p0 = *(const float2*)&B0[(mb + g)     * PN + c0];
            float2 p1 = *(const float2*)&B0[(mb + g + 8) * PN + c0];
            *(float2*)&B0[(mb + g)     * PN + c0] =
                make_float2(1.5f * p0.x - 0.5f * a4[j][0], 1.5f * p0.y - 0.5f * a4[j][1]);
            *(float2*)&B0[(mb + g + 8) * PN + c0] =
                make_float2(1.5f * p1.x - 0.5f * a4[j][2], 1.5f * p1.y - 0.5f * a4[j][3]);
        }
        __syncthreads();
    }

    u64 acc[2][2], acc2[2][2];
    for (int it = 0; it < NS_FP; it++) {
        mm_sym2(B0, B0, ib, jb, acc);
        mm_sym2(B0, B1, ib, jb, acc2);
#pragma unroll
        for (int ii = 0; ii < 2; ii++) {
            float2 l0 = unpk(acc[ii][0]);
            float2 l1 = unpk(acc[ii][1]);
            *(float4*)&B2[(ib + ii) * PN + jb] = make_float4(l0.x, l0.y, l1.x, l1.y);
            float2 m0 = unpk(acc2[ii][0]);
            float2 m1 = unpk(acc2[ii][1]);
            *(float4*)&B3[(ib + ii) * PN + jb] = make_float4(m0.x, m0.y, m1.x, m1.y);
        }
        __syncthreads();
        mm_sym2(B2, B3, ib, jb, acc);
#pragma unroll
        for (int ii = 0; ii < 2; ii++) {
            float2 l0 = unpk(acc[ii][0]);
            float2 l1 = unpk(acc[ii][1]);
            int base = (ib + ii) * PN + jb;
            float4 p = *(const float4*)&B0[base];
            *(float4*)&B0[base] = make_float4(1.5f * p.x - 0.5f * l0.x,
                                              1.5f * p.y - 0.5f * l0.y,
                                              1.5f * p.z - 0.5f * l1.x,
                                              1.5f * p.w - 0.5f * l1.y);
        }
        __syncthreads();
    }

#pragma unroll
    for (int ii = 0; ii < 2; ii++) {
        float4 p = *(const float4*)&B0[(ib + ii) * PN + jb];
        *(float4*)&d_wm[(ib + ii) * 64 + jb] =
            make_float4(p.x * srt, p.y * srt, p.z * srt, p.w * srt);
    }
    if (tid < 64) {
        float s = 0.f;
#pragma unroll 8
        for (int j = 0; j < 64; j++) s += B0[tid * PN + j] * (d_sums[j] * inv_m);
        d_off[tid] = beta[tid] - srt * s;
    }
}

// ---------------------------------------------------------------------------
// Kernel 3: out = x + E@x + off. TMA loads/stores; x+off folded into C-init.
// (R12 apply, unchanged.)
// ---------------------------------------------------------------------------
__global__ __launch_bounds__(256, 2) void apply_kernel(
        const __grid_constant__ CUtensorMap tmX,
        const __grid_constant__ CUtensorMap tmO) {
    __shared__ float raw[5 * 4096 + 256];
    __shared__ float osh[64];
    __shared__ u64 mbar[3];
    float* xbase = (float*)(((uintptr_t)raw + 1023) & ~(uintptr_t)1023);
    float* ybase = xbase + 3 * 4096;

    int tid = threadIdx.x, lane = tid & 31, w = tid >> 5;
    int g = lane >> 2, t = lane & 3;
    int mb = (w & 1) * 32, nb = (w >> 1) * 16;

    uint32_t sb[3], mbr[3], yb[2];
#pragma unroll
    for (int i = 0; i < 3; i++) {
        sb[i]  = (uint32_t)__cvta_generic_to_shared(xbase + i * 4096);
        mbr[i] = (uint32_t)__cvta_generic_to_shared(&mbar[i]);
    }
    yb[0] = (uint32_t)__cvta_generic_to_shared(ybase);
    yb[1] = (uint32_t)__cvta_generic_to_shared(ybase + 4096);

    if (tid == 0) { mbar_init(mbr[0], 1); mbar_init(mbr[1], 1); mbar_init(mbr[2], 1); }

    uint32_t ea[2][8][4];
#pragma unroll
    for (int mi = 0; mi < 2; mi++) {
        int r0 = mb + 16 * mi + g, r1 = r0 + 8;
#pragma unroll
        for (int ks = 0; ks < 8; ks++) {
            int c0 = 8 * ks + t, c1 = c0 + 4;
            ea[mi][ks][0] = tf32r(d_wm[r0 * 64 + c0] - (r0 == c0 ? 1.f : 0.f));
            ea[mi][ks][1] = tf32r(d_wm[r1 * 64 + c0] - (r1 == c0 ? 1.f : 0.f));
            ea[mi][ks][2] = tf32r(d_wm[r0 * 64 + c1] - (r0 == c1 ? 1.f : 0.f));
            ea[mi][ks][3] = tf32r(d_wm[r1 * 64 + c1] - (r1 == c1 ? 1.f : 0.f));
        }
    }
    if (tid < 64) osh[tid] = d_off[tid];
    __syncthreads();

    float orow[2][2];
#pragma unroll
    for (int mi = 0; mi < 2; mi++) {
        orow[mi][0] = osh[mb + 16 * mi + g];
        orow[mi][1] = osh[mb + 16 * mi + g + 8];
    }

    if (tid == 0) {
#pragma unroll
        for (int p = 0; p < 2; p++)
            load_chunk(sb[p], &tmX, blockIdx.x + p * GRIDB, mbr[p]);
    }

    int ph[3] = {0, 0, 0};
    int it = 0;
    for (int ch = blockIdx.x; ch < NCHUNK; ch += GRIDB, it++) {
        int s = it % 3;
        if (tid == 0) tma_wait<1>();
        mbar_wait(mbr[s], ph[s]); ph[s] ^= 1;
        __syncthreads();

        int cn = ch + 2 * GRIDB;
        if (cn < NCHUNK && tid == 0) {
            int sn = (it + 2) % 3;
            load_chunk(sb[sn], &tmX, cn, mbr[sn]);
        }

        const float* xb = xbase + s * 4096;
        float* yw = ybase + (it & 1) * 4096;

        float acc[2][2][4];
#pragma unroll
        for (int mi = 0; mi < 2; mi++) {
            int r0 = mb + 16 * mi + g, r1 = r0 + 8;
#pragma unroll
            for (int j = 0; j < 2; j++) {
                int cc = nb + 8 * j + 2 * t;
                float2 v0 = *(const float2*)&xb[swidx(r0, cc)];
                float2 v1 = *(const float2*)&xb[swidx(r1, cc)];
                acc[mi][j][0] = orow[mi][0] + v0.x;
                acc[mi][j][1] = orow[mi][0] + v0.y;
                acc[mi][j][2] = orow[mi][1] + v1.x;
                acc[mi][j][3] = orow[mi][1] + v1.y;
            }
        }

#pragma unroll
        for (int ks = 0; ks < 8; ks++) {
            uint32_t b00 = fu(xb[swidx(8 * ks + t,     nb + g)]);
            uint32_t b01 = fu(xb[swidx(8 * ks + t + 4, nb + g)]);
            uint32_t b10 = fu(xb[swidx(8 * ks + t,     nb + 8 + g)]);
            uint32_t b11 = fu(xb[swidx(8 * ks + t + 4, nb + 8 + g)]);
#pragma unroll
            for (int mi = 0; mi < 2; mi++) {
                mma8(acc[mi][0], ea[mi][ks][0], ea[mi][ks][1],
                                 ea[mi][ks][2], ea[mi][ks][3], b00, b01);
                mma8(acc[mi][1], ea[mi][ks][0], ea[mi][ks][1],
                                 ea[mi][ks][2], ea[mi][ks][3], b10, b11);
            }
        }
#pragma unroll
        for (int mi = 0; mi < 2; mi++) {
            int r0 = mb + 16 * mi + g, r1 = r0 + 8;
#pragma unroll
            for (int j = 0; j < 2; j++) {
                int cc = nb + 8 * j + 2 * t;
                *(float2*)&yw[swidx(r0, cc)] = make_float2(acc[mi][j][0], acc[mi][j][1]);
                *(float2*)&yw[swidx(r1, cc)] = make_float2(acc[mi][j][2], acc[mi][j][3]);
            }
        }
        __syncthreads();

        if (tid == 0) {
            fence_async();
            int b = ch / CPI, pc = (ch - b * CPI) * 64;
            uint32_t ys = yb[it & 1];
            tma_st(&tmO, pc,      0, b, ys);
            tma_st(&tmO, pc + 32, 0, b, ys + 8192);
            tma_commit();
        }
    }
    if (tid == 0) tma_wait<0>();
}

// ---------------------------------------------------------------------------
typedef CUresult (CUDAAPI *PFN_tmEnc)(CUtensorMap*, CUtensorMapDataType, cuuint32_t,
                                      void*, const cuuint64_t*, const cuuint64_t*,
                                      const cuuint32_t*, const cuuint32_t*,
                                      CUtensorMapInterleave, CUtensorMapSwizzle,
                                      CUtensorMapL2promotion, CUtensorMapFloatOOBfill);

extern "C" void kernel_launch(void* const* d_in, const int* in_sizes, int n_in,
                              void* d_out, int out_size) {
    (void)in_sizes; (void)n_in; (void)out_size;
    const float* X    = (const float*)d_in[0];
    const float* beta = (const float*)d_in[1];
    float* out        = (float*)d_out;

    PFN_tmEnc enc = nullptr;
    cudaDriverEntryPointQueryResult qr;
    cudaGetDriverEntryPoint("cuTensorMapEncodeTiled", (void**)&enc,
                            cudaEnableDefault, &qr);

    CUtensorMap tmX, tmO;
    cuuint64_t dims[3]    = {(cuuint64_t)HWP, (cuuint64_t)CCH, (cuuint64_t)NBATCH};
    cuuint64_t strides[2] = {(cuuint64_t)HWP * 4ull,
                             (cuuint64_t)CCH * (cuuint64_t)HWP * 4ull};
    cuuint32_t box[3] = {32u, 64u, 1u};
    cuuint32_t es[3]  = {1u, 1u, 1u};
    enc(&tmX, CU_TENSOR_MAP_DATA_TYPE_FLOAT32, 3, (void*)X, dims, strides, box, es,
        CU_TENSOR_MAP_INTERLEAVE_NONE, CU_TENSOR_MAP_SWIZZLE_128B,
        CU_TENSOR_MAP_L2_PROMOTION_L2_128B, CU_TENSOR_MAP_FLOAT_OOB_FILL_NONE);
    enc(&tmO, CU_TENSOR_MAP_DATA_TYPE_FLOAT32, 3, (void*)out, dims, strides, box, es,
        CU_TENSOR_MAP_INTERLEAVE_NONE, CU_TENSOR_MAP_SWIZZLE_128B,
        CU_TENSOR_MAP_L2_PROMOTION_L2_128B, CU_TENSOR_MAP_FLOAT_OOB_FILL_NONE);

    zero_scratch<<<16, 256>>>();
    gram_kernel<<<GRIDB, 256>>>(tmX);
    reduce_kernel<<<264, 128>>>();
    ns_kernel<<<1, 512>>>(beta);
    apply_kernel<<<GRIDB, 256>>>(tmX, tmO);
}

// round 15
// speedup vs baseline: 1.3593x; 1.0417x over previous
#include <cuda_runtime.h>
#include <cuda.h>
#include <math.h>
#include <stdint.h>

#define CCH    64
#define HWP    3136
#define NBATCH 128
#define MTOT   401408
#define CPI    49
#define NCHUNK 6272
#define GRIDB  296
#define PN     68
#define NS_TF  6
#define RCPG   37           // CTAs per reduce group (8*37=296)

typedef unsigned long long u64;

__device__ float d_gpart[GRIDB * 4096];
__device__ float d_spart[GRIDB * 64];
__device__ float d_qpart[GRIDB * 64];
__device__ float d_gram[4096];
__device__ float d_sums[64];
__device__ float d_sumsq[64];
__device__ float d_wm[4096];
__device__ float d_off[64];

// ---- swizzled tile indexing (TMA SW128, box 32x64 f32, halves at 0/8KB) ----
__device__ __forceinline__ int swidx(int c, int p) {
    return ((p >> 5) << 11) + (c << 5) + ((p & 31) ^ ((c & 7) << 2));
}

// ---- helpers ---------------------------------------------------------------
__device__ __forceinline__ uint32_t fu(float x) { return __float_as_uint(x); }
__device__ __forceinline__ uint32_t tf32r(float x) {
    uint32_t r; asm("cvt.rna.tf32.f32 %0, %1;" : "=r"(r) : "f"(x)); return r;
}
__device__ __forceinline__ void mma8(float c[4], uint32_t a0, uint32_t a1,
                                     uint32_t a2, uint32_t a3,
                                     uint32_t b0, uint32_t b1) {
    asm("mma.sync.aligned.m16n8k8.row.col.f32.tf32.tf32.f32 "
        "{%0,%1,%2,%3}, {%4,%5,%6,%7}, {%8,%9}, {%0,%1,%2,%3};"
        : "+f"(c[0]), "+f"(c[1]), "+f"(c[2]), "+f"(c[3])
        : "r"(a0), "r"(a1), "r"(a2), "r"(a3), "r"(b0), "r"(b1));
}
__device__ __forceinline__ void fma2(u64 &acc, u64 a, u64 b) {
    asm("fma.rn.f32x2 %0, %1, %2, %0;" : "+l"(acc) : "l"(a), "l"(b));
}
__device__ __forceinline__ u64 dup2(float x) {
    u64 r; asm("mov.b64 %0, {%1, %1};" : "=l"(r) : "r"(__float_as_uint(x))); return r;
}
__device__ __forceinline__ float2 unpk(u64 v) {
    float2 f; asm("mov.b64 {%0, %1}, %2;" : "=f"(f.x), "=f"(f.y) : "l"(v)); return f;
}
// ---- TMA machinery ---------------------------------------------------------
__device__ __forceinline__ void mbar_init(uint32_t mb, uint32_t cnt) {
    asm volatile("mbarrier.init.shared.b64 [%0], %1;" :: "r"(mb), "r"(cnt) : "memory");
}
__device__ __forceinline__ void mbar_expect(uint32_t mb, uint32_t bytes) {
    asm volatile("mbarrier.arrive.expect_tx.shared.b64 _, [%0], %1;"
                 :: "r"(mb), "r"(bytes) : "memory");
}
__device__ __forceinline__ void mbar_wait(uint32_t mb, uint32_t parity) {
    uint32_t done;
    do {
        asm volatile("{\n\t.reg .pred p;\n\t"
                     "mbarrier.try_wait.parity.acquire.cta.shared::cta.b64 p, [%1], %2, 0x989680;\n\t"
                     "selp.b32 %0, 1, 0, p;\n\t}"
                     : "=r"(done) : "r"(mb), "r"(parity) : "memory");
    } while (!done);
}
__device__ __forceinline__ void tma_ld(uint32_t dst, const CUtensorMap* tm,
                                       int x, int y, int z, uint32_t mb) {
    asm volatile("cp.async.bulk.tensor.3d.shared::cta.global.tile.mbarrier::complete_tx::bytes "
                 "[%0], [%1, {%2, %3, %4}], [%5];"
                 :: "r"(dst), "l"(tm), "r"(x), "r"(y), "r"(z), "r"(mb) : "memory");
}
__device__ __forceinline__ void tma_st(const CUtensorMap* tm, int x, int y, int z,
                                       uint32_t src) {
    asm volatile("cp.async.bulk.tensor.3d.global.shared::cta.tile.bulk_group "
                 "[%0, {%1, %2, %3}], [%4];"
                 :: "l"(tm), "r"(x), "r"(y), "r"(z), "r"(src) : "memory");
}
__device__ __forceinline__ void tma_commit() {
    asm volatile("cp.async.bulk.commit_group;" ::: "memory");
}
template<int N> __device__ __forceinline__ void tma_wait() {
    asm volatile("cp.async.bulk.wait_group %0;" :: "n"(N) : "memory");
}
__device__ __forceinline__ void fence_async() {
    asm volatile("fence.proxy.async;" ::: "memory");
}
__device__ __forceinline__ void load_chunk(uint32_t dst, const CUtensorMap* tm,
                                           int ch, uint32_t mb) {
    int b = ch / CPI, pc = (ch - b * CPI) * 64;
    mbar_expect(mb, 16384u);
    tma_ld(dst,        tm, pc,      0, b, mb);
    tma_ld(dst + 8192, tm, pc + 32, 0, b, mb);
}

__global__ void zero_scratch() {
    int i = blockIdx.x * 256 + threadIdx.x;
    if (i < 4096) d_gram[i] = 0.f;
    if (i < 64)   { d_sums[i] = 0.f; d_sumsq[i] = 0.f; }
}

// ---------------------------------------------------------------------------
// Kernel 1: Gram via tf32 mma, TMA-loaded chunks. Sums spread over 256 thr.
// ---------------------------------------------------------------------------
__global__ __launch_bounds__(256, 2) void gram_kernel(const __grid_constant__ CUtensorMap tmX) {
    __shared__ float raw_x[3 * 4096 + 256];
    __shared__ u64 mbar[3];
    float* xbase = (float*)(((uintptr_t)raw_x + 1023) & ~(uintptr_t)1023);

    int tid = threadIdx.x, lane = tid & 31, w = tid >> 5;
    int g = lane >> 2, t = lane & 3;
    int mb = (w & 3) * 16, nb = (w >> 2) * 32;
    int sc = tid >> 2, st = tid & 3;

    uint32_t sb[3], mbr[3];
#pragma unroll
    for (int i = 0; i < 3; i++) {
        sb[i]  = (uint32_t)__cvta_generic_to_shared(xbase + i * 4096);
        mbr[i] = (uint32_t)__cvta_generic_to_shared(&mbar[i]);
    }
    if (tid == 0) { mbar_init(mbr[0], 1); mbar_init(mbr[1], 1); mbar_init(mbr[2], 1); }
    __syncthreads();

    float acc[4][4];
#pragma unroll
    for (int j = 0; j < 4; j++)
#pragma unroll
        for (int e = 0; e < 4; e++) acc[j][e] = 0.f;
    float csum = 0.f, cq = 0.f;

    if (tid == 0) {
#pragma unroll
        for (int p = 0; p < 2; p++)
            load_chunk(sb[p], &tmX, blockIdx.x + p * GRIDB, mbr[p]);
    }

    int ph[3] = {0, 0, 0};
    int it = 0;
    for (int ch = blockIdx.x; ch < NCHUNK; ch += GRIDB, it++) {
        int s = it % 3;
        mbar_wait(mbr[s], ph[s]); ph[s] ^= 1;
        __syncthreads();

        int cn = ch + 2 * GRIDB;
        if (cn < NCHUNK && tid == 0) {
            int sn = (it + 2) % 3;
            load_chunk(sb[sn], &tmX, cn, mbr[sn]);
        }

        const float* xb = xbase + s * 4096;

        {
            float sv = 0.f, q2 = 0.f;
#pragma unroll
            for (int qq = 0; qq < 4; qq++) {
                float4 v = *(const float4*)&xb[swidx(sc, (st * 4 + qq) * 4)];
                sv += (v.x + v.y) + (v.z + v.w);
                q2 += v.x * v.x + v.y * v.y + v.z * v.z + v.w * v.w;
            }
            csum += sv; cq += q2;
        }

#pragma unroll
        for (int kg = 0; kg < 2; kg++) {
            int kb = kg * 32;
            float4 Al  = *(const float4*)&xb[swidx(mb + g,     kb + 4 * t)];
            float4 Ah  = *(const float4*)&xb[swidx(mb + g,     kb + 16 + 4 * t)];
            float4 A2l = *(const float4*)&xb[swidx(mb + g + 8, kb + 4 * t)];
            float4 A2h = *(const float4*)&xb[swidx(mb + g + 8, kb + 16 + 4 * t)];
#pragma unroll
            for (int j = 0; j < 4; j++) {
                float4 Bl = *(const float4*)&xb[swidx(nb + 8 * j + g, kb + 4 * t)];
                float4 Bh = *(const float4*)&xb[swidx(nb + 8 * j + g, kb + 16 + 4 * t)];
                mma8(acc[j], fu(Al.x), fu(A2l.x), fu(Ah.x), fu(A2h.x), fu(Bl.x), fu(Bh.x));
                mma8(acc[j], fu(Al.y), fu(A2l.y), fu(Ah.y), fu(A2h.y), fu(Bl.y), fu(Bh.y));
                mma8(acc[j], fu(Al.z), fu(A2l.z), fu(Ah.z), fu(A2h.z), fu(Bl.z), fu(Bh.z));
                mma8(acc[j], fu(Al.w), fu(A2l.w), fu(Ah.w), fu(A2h.w), fu(Bl.w), fu(Bh.w));
            }
        }
    }

    float* gp = &d_gpart[blockIdx.x * 4096];
#pragma unroll
    for (int j = 0; j < 4; j++) {
        int col = nb + 8 * j + 2 * t;
        gp[(mb + g)     * 64 + col]     = acc[j][0];
        gp[(mb + g)     * 64 + col + 1] = acc[j][1];
        gp[(mb + g + 8) * 64 + col]     = acc[j][2];
        gp[(mb + g + 8) * 64 + col + 1] = acc[j][3];
    }
    csum += __shfl_xor_sync(0xffffffffu, csum, 1);
    csum += __shfl_xor_sync(0xffffffffu, csum, 2);
    cq   += __shfl_xor_sync(0xffffffffu, cq, 1);
    cq   += __shfl_xor_sync(0xffffffffu, cq, 2);
    if (st == 0) {
        d_spart[blockIdx.x * 64 + sc] = csum;
        d_qpart[blockIdx.x * 64 + sc] = cq;
    }
}

// ---------------------------------------------------------------------------
// Kernel 1b: hierarchical reduce — 8 groups x 37 CTAs, 8-way atomics.
// ---------------------------------------------------------------------------
__global__ __launch_bounds__(128) void reduce_kernel() {
    int grp = blockIdx.x / 33;
    int blk = blockIdx.x - grp * 33;
    int idx = blk * 128 + threadIdx.x;
    int c0 = grp * RCPG;
    if (idx < 4096) {
        float s = 0.f;
#pragma unroll 4
        for (int c = 0; c < RCPG; c++) s += d_gpart[(c0 + c) * 4096 + idx];
        atomicAdd(&d_gram[idx], s);
    } else if (idx < 4160) {
        int j = idx - 4096;
        float s = 0.f;
#pragma unroll 4
        for (int c = 0; c < RCPG; c++) s += d_spart[(c0 + c) * 64 + j];
        atomicAdd(&d_sums[j], s);
    } else if (idx < 4224) {
        int j = idx - 4160;
        float s = 0.f;
#pragma unroll 4
        for (int c = 0; c < RCPG; c++) s += d_qpart[(c0 + c) * 64 + j];
        atomicAdd(&d_sumsq[j], s);
    }
}

// ---------------------------------------------------------------------------
// Kernel 2: Sigma + Newton-Schulz. 512 threads; fused stage-1 (Sigma_N frags
// register-resident), split-chain stage-2, 6 tf32 + 1 exact iterations.
// ---------------------------------------------------------------------------
__device__ __forceinline__ void mm_sym2(const float* __restrict__ A,
                                        const float* __restrict__ Bm,
                                        int ib, int jb, u64 acc[2][2]) {
#pragma unroll
    for (int ii = 0; ii < 2; ii++) { acc[ii][0] = 0ull; acc[ii][1] = 0ull; }
#pragma unroll 8
    for (int k = 0; k < 64; k++) {
        float2 a = *(const float2*)&A[k * PN + ib];
        ulonglong2 bv = *(const ulonglong2*)&Bm[k * PN + jb];
        u64 d0 = dup2(a.x), d1 = dup2(a.y);
        fma2(acc[0][0], d0, bv.x); fma2(acc[0][1], d0, bv.y);
        fma2(acc[1][0], d1, bv.x); fma2(acc[1][1], d1, bv.y);
    }
}

__global__ __launch_bounds__(512) void ns_kernel(const float* __restrict__ beta) {
    __shared__ __align__(16) float B0[64 * PN];
    __shared__ __align__(16) float B1[64 * PN];
    __shared__ __align__(16) float B2[64 * PN];
    __shared__ __align__(16) float B3[64 * PN];
    int tid = threadIdx.x, lane = tid & 31, w = tid >> 5;
    int g = lane >> 2, t = lane & 3;
    int mb = (w & 3) * 16, nb = (w >> 2) * 16;
    int ib = (tid >> 4) * 2, jb = (tid & 15) * 4;
    const float inv_m = 1.f / (float)MTOT;

    for (int idx = tid; idx < 4096; idx += 512) {
        int i = idx >> 6, j = idx & 63;
        float mi = d_sums[i] * inv_m, mj = d_sums[j] * inv_m;
        float s;
        if (i == j) s = d_sumsq[i] * inv_m - mi * mi + 1e-5f;
        else        s = (d_gram[idx] * inv_m - mi * mj) * 0.9f;
        B1[i * PN + j] = s;
    }
    __syncthreads();

    if (tid < 32) {
        float s = B1[tid * PN + tid] + B1[(tid + 32) * PN + (tid + 32)];
#pragma unroll
        for (int o = 16; o > 0; o >>= 1) s += __shfl_xor_sync(0xffffffffu, s, o);
        if (tid == 0) B2[0] = s;
    }
    __syncthreads();
    float rTr = 1.f / B2[0];
    float srt = sqrtf(rTr);
    __syncthreads();

    for (int idx = tid; idx < 4096; idx += 512) {
        int i = idx >> 6, j = idx & 63;
        float sn = B1[i * PN + j] * rTr;
        B1[i * PN + j] = sn;
        B0[i * PN + j] = (i == j ? 1.5f : 0.f) - 0.5f * sn;
    }
    __syncthreads();

    // register-resident Sigma_N B-fragments (constant across iterations)
    uint32_t sfb[8][2][2];
#pragma unroll
    for (int ks = 0; ks < 8; ks++)
#pragma unroll
        for (int j = 0; j < 2; j++) {
            sfb[ks][j][0] = fu(B1[(8 * ks + t)     * PN + nb + 8 * j + g]);
            sfb[ks][j][1] = fu(B1[(8 * ks + t + 4) * PN + nb + 8 * j + g]);
        }

    for (int it = 0; it < NS_TF; it++) {
        // stage 1 (fused): T1 = P@P, T2 = P@Sigma_N — 4 independent mma chains
        float t1[2][4], t2[2][4];
#pragma unroll
        for (int j = 0; j < 2; j++)
#pragma unroll
            for (int e = 0; e < 4; e++) { t1[j][e] = 0.f; t2[j][e] = 0.f; }
#pragma unroll
        for (int ks = 0; ks < 8; ks++) {
            uint32_t a0 = fu(B0[(mb + g)     * PN + 8 * ks + t]);
            uint32_t a1 = fu(B0[(mb + g + 8) * PN + 8 * ks + t]);
            uint32_t a2 = fu(B0[(mb + g)     * PN + 8 * ks + t + 4]);
            uint32_t a3 = fu(B0[(mb + g + 8) * PN + 8 * ks + t + 4]);
#pragma unroll
            for (int j = 0; j < 2; j++) {
                uint32_t b0 = fu(B0[(8 * ks + t)     * PN + nb + 8 * j + g]);
                uint32_t b1 = fu(B0[(8 * ks + t + 4) * PN + nb + 8 * j + g]);
                mma8(t1[j], a0, a1, a2, a3, b0, b1);
                mma8(t2[j], a0, a1, a2, a3, sfb[ks][j][0], sfb[ks][j][1]);
            }
        }
#pragma unroll
        for (int j = 0; j < 2; j++) {
            int c0 = nb + 8 * j + 2 * t;
            *(float2*)&B2[(mb + g)     * PN + c0] = make_float2(t1[j][0], t1[j][1]);
            *(float2*)&B2[(mb + g + 8) * PN + c0] = make_float2(t1[j][2], t1[j][3]);
            *(float2*)&B3[(mb + g)     * PN + c0] = make_float2(t2[j][0], t2[j][1]);
            *(float2*)&B3[(mb + g + 8) * PN + c0] = make_float2(t2[j][2], t2[j][3]);
        }
        __syncthreads();

        // stage 2: P = 1.5P - 0.5 * T1@T2 — split chains (depth 4)
        float u0[2][4], u1[2][4];
#pragma unroll
        for (int j = 0; j < 2; j++)
#pragma unroll
            for (int e = 0; e < 4; e++) { u0[j][e] = 0.f; u1[j][e] = 0.f; }
#pragma unroll
        for (int ks = 0; ks < 8; ks++) {
            uint32_t a0 = fu(B2[(mb + g)     * PN + 8 * ks + t]);
            uint32_t a1 = fu(B2[(mb + g + 8) * PN + 8 * ks + t]);
            uint32_t a2 = fu(B2[(mb + g)     * PN + 8 * ks + t + 4]);
            uint32_t a3 = fu(B2[(mb + g + 8) * PN + 8 * ks + t + 4]);
#pragma unroll
            for (int j = 0; j < 2; j++) {
                uint32_t b0 = fu(B3[(8 * ks + t)     * PN + nb + 8 * j + g]);
                uint32_t b1 = fu(B3[(8 * ks + t + 4) * PN + nb + 8 * j + g]);
                if (ks < 4) mma8(u0[j], a0, a1, a2, a3, b0, b1);
                else        mma8(u1[j], a0, a1, a2, a3, b0, b1);
            }
        }
#pragma unroll
        for (int j = 0; j < 2; j++) {
            int c0 = nb + 8 * j + 2 * t;
            float s0 = u0[j][0] + u1[j][0], s1 = u0[j][1] + u1[j][1];
            float s2 = u0[j][2] + u1[j][2], s3 = u0[j][3] + u1[j][3];
            float2 p0 = *(const float2*)&B0[(mb + g)     * PN + c0];
            float2 p1 = *(const float2*)&B0[(mb + g + 8) * PN + c0];
            *(float2*)&B0[(mb + g)     * PN + c0] =
                make_float2(1.5f * p0.x - 0.5f * s0, 1.5f * p0.y - 0.5f * s1);
            *(float2*)&B0[(mb + g + 8) * PN + c0] =
                make_float2(1.5f * p1.x - 0.5f * s2, 1.5f * p1.y - 0.5f * s3);
        }
        __syncthreads();
    }

    // exact fp32 final iteration (f32x2)
    u64 acc[2][2], acc2[2][2];
    {
        mm_sym2(B0, B0, ib, jb, acc);
        mm_sym2(B0, B1, ib, jb, acc2);
#pragma unroll
        for (int ii = 0; ii < 2; ii++) {
            float2 l0 = unpk(acc[ii][0]);
            float2 l1 = unpk(acc[ii][1]);
            *(float4*)&B2[(ib + ii) * PN + jb] = make_float4(l0.x, l0.y, l1.x, l1.y);
            float2 m0 = unpk(acc2[ii][0]);
            float2 m1 = unpk(acc2[ii][1]);
            *(float4*)&B3[(ib + ii) * PN + jb] = make_float4(m0.x, m0.y, m1.x, m1.y);
        }
        __syncthreads();
        mm_sym2(B2, B3, ib, jb, acc);
#pragma unroll
        for (int ii = 0; ii < 2; ii++) {
            float2 l0 = unpk(acc[ii][0]);
            float2 l1 = unpk(acc[ii][1]);
            int base = (ib + ii) * PN + jb;
            float4 p = *(const float4*)&B0[base];
            *(float4*)&B0[base] = make_float4(1.5f * p.x - 0.5f * l0.x,
                                              1.5f * p.y - 0.5f * l0.y,
                                              1.5f * p.z - 0.5f * l1.x,
                                              1.5f * p.w - 0.5f * l1.y);
        }
        __syncthreads();
    }

#pragma unroll
    for (int ii = 0; ii < 2; ii++) {
        float4 p = *(const float4*)&B0[(ib + ii) * PN + jb];
        *(float4*)&d_wm[(ib + ii) * 64 + jb] =
            make_float4(p.x * srt, p.y * srt, p.z * srt, p.w * srt);
    }
    if (tid < 64) {
        float s = 0.f;
#pragma unroll 8
        for (int j = 0; j < 64; j++) s += B0[tid * PN + j] * (d_sums[j] * inv_m);
        d_off[tid] = beta[tid] - srt * s;
    }
}

// ---------------------------------------------------------------------------
// Kernel 3: out = x + E@x + off. TMA loads/stores; x+off folded into C-init.
// ---------------------------------------------------------------------------
__global__ __launch_bounds__(256, 2) void apply_kernel(
        const __grid_constant__ CUtensorMap tmX,
        const __grid_constant__ CUtensorMap tmO) {
    __shared__ float raw[5 * 4096 + 256];
    __shared__ float osh[64];
    __shared__ u64 mbar[3];
    float* xbase = (float*)(((uintptr_t)raw + 1023) & ~(uintptr_t)1023);
    float* ybase = xbase + 3 * 4096;

    int tid = threadIdx.x, lane = tid & 31, w = tid >> 5;
    int g = lane >> 2, t = lane & 3;
    int mb = (w & 1) * 32, nb = (w >> 1) * 16;

    uint32_t sb[3], mbr[3], yb[2];
#pragma unroll
    for (int i = 0; i < 3; i++) {
        sb[i]  = (uint32_t)__cvta_generic_to_shared(xbase + i * 4096);
        mbr[i] = (uint32_t)__cvta_generic_to_shared(&mbar[i]);
    }
    yb[0] = (uint32_t)__cvta_generic_to_shared(ybase);
    yb[1] = (uint32_t)__cvta_generic_to_shared(ybase + 4096);

    if (tid == 0) { mbar_init(mbr[0], 1); mbar_init(mbr[1], 1); mbar_init(mbr[2], 1); }

    uint32_t ea[2][8][4];
#pragma unroll
    for (int mi = 0; mi < 2; mi++) {
        int r0 = mb + 16 * mi + g, r1 = r0 + 8;
#pragma unroll
        for (int ks = 0; ks < 8; ks++) {
            int c0 = 8 * ks + t, c1 = c0 + 4;
            ea[mi][ks][0] = tf32r(d_wm[r0 * 64 + c0] - (r0 == c0 ? 1.f : 0.f));
            ea[mi][ks][1] = tf32r(d_wm[r1 * 64 + c0] - (r1 == c0 ? 1.f : 0.f));
            ea[mi][ks][2] = tf32r(d_wm[r0 * 64 + c1] - (r0 == c1 ? 1.f : 0.f));
            ea[mi][ks][3] = tf32r(d_wm[r1 * 64 + c1] - (r1 == c1 ? 1.f : 0.f));
        }
    }
    if (tid < 64) osh[tid] = d_off[tid];
    __syncthreads();

    float orow[2][2];
#pragma unroll
    for (int mi = 0; mi < 2; mi++) {
        orow[mi][0] = osh[mb + 16 * mi + g];
        orow[mi][1] = osh[mb + 16 * mi + g + 8];
    }

    if (tid == 0) {
#pragma unroll
        for (int p = 0; p < 2; p++)
            load_chunk(sb[p], &tmX, blockIdx.x + p * GRIDB, mbr[p]);
    }

    int ph[3] = {0, 0, 0};
    int it = 0;
    for (int ch = blockIdx.x; ch < NCHUNK; ch += GRIDB, it++) {
        int s = it % 3;
        if (tid == 0) tma_wait<1>();
        mbar_wait(mbr[s], ph[s]); ph[s] ^= 1;
        __syncthreads();

        int cn = ch + 2 * GRIDB;
        if (cn < NCHUNK && tid == 0) {
            int sn = (it + 2) % 3;
            load_chunk(sb[sn], &tmX, cn, mbr[sn]);
        }

        const float* xb = xbase + s * 4096;
        float* yw = ybase + (it & 1) * 4096;

        float acc[2][2][4];
#pragma unroll
        for (int mi = 0; mi < 2; mi++) {
            int r0 = mb + 16 * mi + g, r1 = r0 + 8;
#pragma unroll
            for (int j = 0; j < 2; j++) {
                int cc = nb + 8 * j + 2 * t;
                float2 v0 = *(const float2*)&xb[swidx(r0, cc)];
                float2 v1 = *(const float2*)&xb[swidx(r1, cc)];
                acc[mi][j][0] = orow[mi][0] + v0.x;
                acc[mi][j][1] = orow[mi][0] + v0.y;
                acc[mi][j][2] = orow[mi][1] + v1.x;
                acc[mi][j][3] = orow[mi][1] + v1.y;
            }
        }

#pragma unroll
        for (int ks = 0; ks < 8; ks++) {
            uint32_t b00 = fu(xb[swidx(8 * ks + t,     nb + g)]);
            uint32_t b01 = fu(xb[swidx(8 * ks + t + 4, nb + g)]);
            uint32_t b10 = fu(xb[swidx(8 * ks + t,     nb + 8 + g)]);
            uint32_t b11 = fu(xb[swidx(8 * ks + t + 4, nb + 8 + g)]);
#pragma unroll
            for (int mi = 0; mi < 2; mi++) {
                mma8(acc[mi][0], ea[mi][ks][0], ea[mi][ks][1],
                                 ea[mi][ks][2], ea[mi][ks][3], b00, b01);
                mma8(acc[mi][1], ea[mi][ks][0], ea[mi][ks][1],
                                 ea[mi][ks][2], ea[mi][ks][3], b10, b11);
            }
        }
#pragma unroll
        for (int mi = 0; mi < 2; mi++) {
            int r0 = mb + 16 * mi + g, r1 = r0 + 8;
#pragma unroll
            for (int j = 0; j < 2; j++) {
                int cc = nb + 8 * j + 2 * t;
                *(float2*)&yw[swidx(r0, cc)] = make_float2(acc[mi][j][0], acc[mi][j][1]);
                *(float2*)&yw[swidx(r1, cc)] = make_float2(acc[mi][j][2], acc[mi][j][3]);
            }
        }
        __syncthreads();

        if (tid == 0) {
            fence_async();
            int b = ch / CPI, pc = (ch - b * CPI) * 64;
            uint32_t ys = yb[it & 1];
            tma_st(&tmO, pc,      0, b, ys);
            tma_st(&tmO, pc + 32, 0, b, ys + 8192);
            tma_commit();
        }
    }
    if (tid == 0) tma_wait<0>();
}

// ---------------------------------------------------------------------------
typedef CUresult (CUDAAPI *PFN_tmEnc)(CUtensorMap*, CUtensorMapDataType, cuuint32_t,
                                      void*, const cuuint64_t*, const cuuint64_t*,
                                      const cuuint32_t*, const cuuint32_t*,
                                      CUtensorMapInterleave, CUtensorMapSwizzle,
                                      CUtensorMapL2promotion, CUtensorMapFloatOOBfill);

extern "C" void kernel_launch(void* const* d_in, const int* in_sizes, int n_in,
                              void* d_out, int out_size) {
    (void)in_sizes; (void)n_in; (void)out_size;
    const float* X    = (const float*)d_in[0];
    const float* beta = (const float*)d_in[1];
    float* out        = (float*)d_out;

    PFN_tmEnc enc = nullptr;
    cudaDriverEntryPointQueryResult qr;
    cudaGetDriverEntryPoint("cuTensorMapEncodeTiled", (void**)&enc,
                            cudaEnableDefault, &qr);

    CUtensorMap tmX, tmO;
    cuuint64_t dims[3]    = {(cuuint64_t)HWP, (cuuint64_t)CCH, (cuuint64_t)NBATCH};
    cuuint64_t strides[2] = {(cuuint64_t)HWP * 4ull,
                             (cuuint64_t)CCH * (cuuint64_t)HWP * 4ull};
    cuuint32_t box[3] = {32u, 64u, 1u};
    cuuint32_t es[3]  = {1u, 1u, 1u};
    enc(&tmX, CU_TENSOR_MAP_DATA_TYPE_FLOAT32, 3, (void*)X, dims, strides, box, es,
        CU_TENSOR_MAP_INTERLEAVE_NONE, CU_TENSOR_MAP_SWIZZLE_128B,
        CU_TENSOR_MAP_L2_PROMOTION_L2_128B, CU_TENSOR_MAP_FLOAT_OOB_FILL_NONE);
    enc(&tmO, CU_TENSOR_MAP_DATA_TYPE_FLOAT32, 3, (void*)out, dims, strides, box, es,
        CU_TENSOR_MAP_INTERLEAVE_NONE, CU_TENSOR_MAP_SWIZZLE_128B,
        CU_TENSOR_MAP_L2_PROMOTION_L2_128B, CU_TENSOR_MAP_FLOAT_OOB_FILL_NONE);

    zero_scratch<<<16, 256>>>();
    gram_kernel<<<GRIDB, 256>>>(tmX);
    reduce_kernel<<<264, 128>>>();
    ns_kernel<<<1, 512>>>(beta);
    apply_kernel<<<GRIDB, 256>>>(tmX, tmO);
}

// round 16
// speedup vs baseline: 1.4227x; 1.0466x over previous
#include <cuda_runtime.h>
#include <cuda.h>
#include <math.h>
#include <stdint.h>

#define CCH    64
#define HWP    3136
#define NBATCH 128
#define MTOT   401408
#define CPI    49
#define NCHUNK 6272
#define GRIDB  296
#define GRIDV  592          // virtual pipelines (2 per CTA)
#define PN     68
#define NS_TF  6
#define RCPG   74           // pipelines per reduce group (8*74=592)

typedef unsigned long long u64;

__device__ float d_gpart[GRIDV * 4096];
__device__ float d_spart[GRIDV * 64];
__device__ float d_qpart[GRIDV * 64];
__device__ float d_gram2[8 * 4096];
__device__ float d_sums2[8 * 64];
__device__ float d_qsum2[8 * 64];
__device__ float d_wm[4096];
__device__ float d_off[64];

// ---- swizzled tile indexing (TMA SW128, box 32x64 f32, halves at 0/8KB) ----
__device__ __forceinline__ int swidx(int c, int p) {
    return ((p >> 5) << 11) + (c << 5) + ((p & 31) ^ ((c & 7) << 2));
}

// ---- helpers ---------------------------------------------------------------
__device__ __forceinline__ uint32_t fu(float x) { return __float_as_uint(x); }
__device__ __forceinline__ uint32_t tf32r(float x) {
    uint32_t r; asm("cvt.rna.tf32.f32 %0, %1;" : "=r"(r) : "f"(x)); return r;
}
__device__ __forceinline__ void mma8(float c[4], uint32_t a0, uint32_t a1,
                                     uint32_t a2, uint32_t a3,
                                     uint32_t b0, uint32_t b1) {
    asm("mma.sync.aligned.m16n8k8.row.col.f32.tf32.tf32.f32 "
        "{%0,%1,%2,%3}, {%4,%5,%6,%7}, {%8,%9}, {%0,%1,%2,%3};"
        : "+f"(c[0]), "+f"(c[1]), "+f"(c[2]), "+f"(c[3])
        : "r"(a0), "r"(a1), "r"(a2), "r"(a3), "r"(b0), "r"(b1));
}
__device__ __forceinline__ void fma2(u64 &acc, u64 a, u64 b) {
    asm("fma.rn.f32x2 %0, %1, %2, %0;" : "+l"(acc) : "l"(a), "l"(b));
}
__device__ __forceinline__ u64 dup2(float x) {
    u64 r; asm("mov.b64 %0, {%1, %1};" : "=l"(r) : "r"(__float_as_uint(x))); return r;
}
__device__ __forceinline__ float2 unpk(u64 v) {
    float2 f; asm("mov.b64 {%0, %1}, %2;" : "=f"(f.x), "=f"(f.y) : "l"(v)); return f;
}
__device__ __forceinline__ void gbar(int id) {
    asm volatile("bar.sync %0, 128;" :: "r"(id) : "memory");
}
// ---- TMA machinery ---------------------------------------------------------
__device__ __forceinline__ void mbar_init(uint32_t mb, uint32_t cnt) {
    asm volatile("mbarrier.init.shared.b64 [%0], %1;" :: "r"(mb), "r"(cnt) : "memory");
}
__device__ __forceinline__ void mbar_expect(uint32_t mb, uint32_t bytes) {
    asm volatile("mbarrier.arrive.expect_tx.shared.b64 _, [%0], %1;"
                 :: "r"(mb), "r"(bytes) : "memory");
}
__device__ __forceinline__ void mbar_wait(uint32_t mb, uint32_t parity) {
    uint32_t done;
    do {
        asm volatile("{\n\t.reg .pred p;\n\t"
                     "mbarrier.try_wait.parity.acquire.cta.shared::cta.b64 p, [%1], %2, 0x989680;\n\t"
                     "selp.b32 %0, 1, 0, p;\n\t}"
                     : "=r"(done) : "r"(mb), "r"(parity) : "memory");
    } while (!done);
}
__device__ __forceinline__ void tma_ld(uint32_t dst, const CUtensorMap* tm,
                                       int x, int y, int z, uint32_t mb) {
    asm volatile("cp.async.bulk.tensor.3d.shared::cta.global.tile.mbarrier::complete_tx::bytes "
                 "[%0], [%1, {%2, %3, %4}], [%5];"
                 :: "r"(dst), "l"(tm), "r"(x), "r"(y), "r"(z), "r"(mb) : "memory");
}
__device__ __forceinline__ void tma_st(const CUtensorMap* tm, int x, int y, int z,
                                       uint32_t src) {
    asm volatile("cp.async.bulk.tensor.3d.global.shared::cta.tile.bulk_group "
                 "[%0, {%1, %2, %3}], [%4];"
                 :: "l"(tm), "r"(x), "r"(y), "r"(z), "r"(src) : "memory");
}
__device__ __forceinline__ void tma_commit() {
    asm volatile("cp.async.bulk.commit_group;" ::: "memory");
}
template<int N> __device__ __forceinline__ void tma_wait() {
    asm volatile("cp.async.bulk.wait_group %0;" :: "n"(N) : "memory");
}
__device__ __forceinline__ void fence_async() {
    asm volatile("fence.proxy.async;" ::: "memory");
}
__device__ __forceinline__ void load_chunk(uint32_t dst, const CUtensorMap* tm,
                                           int ch, uint32_t mb) {
    int b = ch / CPI, pc = (ch - b * CPI) * 64;
    mbar_expect(mb, 16384u);
    tma_ld(dst,        tm, pc,      0, b, mb);
    tma_ld(dst + 8192, tm, pc + 32, 0, b, mb);
}

// ---------------------------------------------------------------------------
// Kernel 1: Gram. 2 warp-groups of 128 threads, each an independent TMA+mma
// pipeline over its own chunk stream (592 virtual pipelines).
// Warp tile: m16 x n64. Sums: 2 lanes/channel within group.
// ---------------------------------------------------------------------------
__global__ __launch_bounds__(256, 2) void gram_kernel(const __grid_constant__ CUtensorMap tmX) {
    __shared__ float raw_x[6 * 4096 + 256];
    __shared__ u64 mbar[6];
    float* xb0 = (float*)(((uintptr_t)raw_x + 1023) & ~(uintptr_t)1023);

    int tid = threadIdx.x;
    int grp = tid >> 7, gt = tid & 127;
    int lane = gt & 31, gw = gt >> 5;
    int g = lane >> 2, t = lane & 3;
    int mb = gw * 16;
    int sc = gt >> 1, st = gt & 1;
    int vc = blockIdx.x * 2 + grp;

    float* xg = xb0 + grp * 3 * 4096;
    uint32_t sb[3], mbr[3];
#pragma unroll
    for (int i = 0; i < 3; i++) {
        sb[i]  = (uint32_t)__cvta_generic_to_shared(xg + i * 4096);
        mbr[i] = (uint32_t)__cvta_generic_to_shared(&mbar[grp * 3 + i]);
    }
    if (gt == 0) { mbar_init(mbr[0], 1); mbar_init(mbr[1], 1); mbar_init(mbr[2], 1); }
    __syncthreads();

    float acc[8][4];
#pragma unroll
    for (int j = 0; j < 8; j++)
#pragma unroll
        for (int e = 0; e < 4; e++) acc[j][e] = 0.f;
    float csum = 0.f, cq = 0.f;

    if (gt == 0) {
#pragma unroll
        for (int p = 0; p < 2; p++)
            load_chunk(sb[p], &tmX, vc + p * GRIDV, mbr[p]);
    }

    int ph[3] = {0, 0, 0};
    int it = 0;
    for (int ch = vc; ch < NCHUNK; ch += GRIDV, it++) {
        int s = it % 3;
        mbar_wait(mbr[s], ph[s]); ph[s] ^= 1;
        gbar(grp + 1);

        int cn = ch + 2 * GRIDV;
        if (cn < NCHUNK && gt == 0) {
            int sn = (it + 2) % 3;
            load_chunk(sb[sn], &tmX, cn, mbr[sn]);
        }

        const float* xb = xg + s * 4096;

        {   // sums/sumsq: 2 lanes per channel, 8 float4 each
            float sv = 0.f, q2 = 0.f;
#pragma unroll
            for (int qq = 0; qq < 8; qq++) {
                float4 v = *(const float4*)&xb[swidx(sc, (st * 8 + qq) * 4)];
                sv += (v.x + v.y) + (v.z + v.w);
                q2 += v.x * v.x + v.y * v.y + v.z * v.z + v.w * v.w;
            }
            csum += sv; cq += q2;
        }

#pragma unroll
        for (int kg = 0; kg < 2; kg++) {
            int kb = kg * 32;
            float4 Al  = *(const float4*)&xb[swidx(mb + g,     kb + 4 * t)];
            float4 Ah  = *(const float4*)&xb[swidx(mb + g,     kb + 16 + 4 * t)];
            float4 A2l = *(const float4*)&xb[swidx(mb + g + 8, kb + 4 * t)];
            float4 A2h = *(const float4*)&xb[swidx(mb + g + 8, kb + 16 + 4 * t)];
#pragma unroll
            for (int j = 0; j < 8; j++) {
                float4 Bl = *(const float4*)&xb[swidx(8 * j + g, kb + 4 * t)];
                float4 Bh = *(const float4*)&xb[swidx(8 * j + g, kb + 16 + 4 * t)];
                mma8(acc[j], fu(Al.x), fu(A2l.x), fu(Ah.x), fu(A2h.x), fu(Bl.x), fu(Bh.x));
                mma8(acc[j], fu(Al.y), fu(A2l.y), fu(Ah.y), fu(A2h.y), fu(Bl.y), fu(Bh.y));
                mma8(acc[j], fu(Al.z), fu(A2l.z), fu(Ah.z), fu(A2h.z), fu(Bl.z), fu(Bh.z));
                mma8(acc[j], fu(Al.w), fu(A2l.w), fu(Ah.w), fu(A2h.w), fu(Bl.w), fu(Bh.w));
            }
        }
    }

    float* gp = &d_gpart[vc * 4096];
#pragma unroll
    for (int j = 0; j < 8; j++) {
        int col = 8 * j + 2 * t;
        gp[(mb + g)     * 64 + col]     = acc[j][0];
        gp[(mb + g)     * 64 + col + 1] = acc[j][1];
        gp[(mb + g + 8) * 64 + col]     = acc[j][2];
        gp[(mb + g + 8) * 64 + col + 1] = acc[j][3];
    }
    csum += __shfl_xor_sync(0xffffffffu, csum, 1);
    cq   += __shfl_xor_sync(0xffffffffu, cq, 1);
    if (st == 0) {
        d_spart[vc * 64 + sc] = csum;
        d_qpart[vc * 64 + sc] = cq;
    }
}

// ---------------------------------------------------------------------------
// Kernel 1b: reduce — 8 groups x 74 pipelines, partial outputs (no atomics).
// ---------------------------------------------------------------------------
__global__ __launch_bounds__(128) void reduce_kernel() {
    int grp = blockIdx.x / 33;
    int blk = blockIdx.x - grp * 33;
    int idx = blk * 128 + threadIdx.x;
    int c0 = grp * RCPG;
    if (idx < 4096) {
        float s = 0.f;
#pragma unroll 4
        for (int c = 0; c < RCPG; c++) s += d_gpart[(c0 + c) * 4096 + idx];
        d_gram2[grp * 4096 + idx] = s;
    } else if (idx < 4160) {
        int j = idx - 4096;
        float s = 0.f;
#pragma unroll 4
        for (int c = 0; c < RCPG; c++) s += d_spart[(c0 + c) * 64 + j];
        d_sums2[grp * 64 + j] = s;
    } else if (idx < 4224) {
        int j = idx - 4160;
        float s = 0.f;
#pragma unroll 4
        for (int c = 0; c < RCPG; c++) s += d_qpart[(c0 + c) * 64 + j];
        d_qsum2[grp * 64 + j] = s;
    }
}

// ---------------------------------------------------------------------------
// Kernel 2: Sigma + Newton-Schulz (R15 structure; sums 8 reduce-partials).
// ---------------------------------------------------------------------------
__device__ __forceinline__ void mm_sym2(const float* __restrict__ A,
                                        const float* __restrict__ Bm,
                                        int ib, int jb, u64 acc[2][2]) {
#pragma unroll
    for (int ii = 0; ii < 2; ii++) { acc[ii][0] = 0ull; acc[ii][1] = 0ull; }
#pragma unroll 8
    for (int k = 0; k < 64; k++) {
        float2 a = *(const float2*)&A[k * PN + ib];
        ulonglong2 bv = *(const ulonglong2*)&Bm[k * PN + jb];
        u64 d0 = dup2(a.x), d1 = dup2(a.y);
        fma2(acc[0][0], d0, bv.x); fma2(acc[0][1], d0, bv.y);
        fma2(acc[1][0], d1, bv.x); fma2(acc[1][1], d1, bv.y);
    }
}

__global__ __launch_bounds__(512) void ns_kernel(const float* __restrict__ beta) {
    __shared__ __align__(16) float B0[64 * PN];
    __shared__ __align__(16) float B1[64 * PN];
    __shared__ __align__(16) float B2[64 * PN];
    __shared__ __align__(16) float B3[64 * PN];
    __shared__ float ssum[64], sq[64];
    int tid = threadIdx.x, lane = tid & 31, w = tid >> 5;
    int g = lane >> 2, t = lane & 3;
    int mb = (w & 3) * 16, nb = (w >> 2) * 16;
    int ib = (tid >> 4) * 2, jb = (tid & 15) * 4;
    const float inv_m = 1.f / (float)MTOT;

    if (tid < 64) {
        float s = 0.f, q = 0.f;
#pragma unroll
        for (int r = 0; r < 8; r++) {
            s += d_sums2[r * 64 + tid];
            q += d_qsum2[r * 64 + tid];
        }
        ssum[tid] = s; sq[tid] = q;
    }
    __syncthreads();

    for (int idx = tid; idx < 4096; idx += 512) {
        int i = idx >> 6, j = idx & 63;
        float gsum = 0.f;
#pragma unroll
        for (int r = 0; r < 8; r++) gsum += d_gram2[r * 4096 + idx];
        float mi = ssum[i] * inv_m, mj = ssum[j] * inv_m;
        float s;
        if (i == j) s = sq[i] * inv_m - mi * mi + 1e-5f;
        else        s = (gsum * inv_m - mi * mj) * 0.9f;
        B1[i * PN + j] = s;
    }
    __syncthreads();

    if (tid < 32) {
        float s = B1[tid * PN + tid] + B1[(tid + 32) * PN + (tid + 32)];
#pragma unroll
        for (int o = 16; o > 0; o >>= 1) s += __shfl_xor_sync(0xffffffffu, s, o);
        if (tid == 0) B2[0] = s;
    }
    __syncthreads();
    float rTr = 1.f / B2[0];
    float srt = sqrtf(rTr);
    __syncthreads();

    for (int idx = tid; idx < 4096; idx += 512) {
        int i = idx >> 6, j = idx & 63;
        float sn = B1[i * PN + j] * rTr;
        B1[i * PN + j] = sn;
        B0[i * PN + j] = (i == j ? 1.5f : 0.f) - 0.5f * sn;
    }
    __syncthreads();

    uint32_t sfb[8][2][2];
#pragma unroll
    for (int ks = 0; ks < 8; ks++)
#pragma unroll
        for (int j = 0; j < 2; j++) {
            sfb[ks][j][0] = fu(B1[(8 * ks + t)     * PN + nb + 8 * j + g]);
            sfb[ks][j][1] = fu(B1[(8 * ks + t + 4) * PN + nb + 8 * j + g]);
        }

    for (int it = 0; it < NS_TF; it++) {
        float t1[2][4], t2[2][4];
#pragma unroll
        for (int j = 0; j < 2; j++)
#pragma unroll
            for (int e = 0; e < 4; e++) { t1[j][e] = 0.f; t2[j][e] = 0.f; }
#pragma unroll
        for (int ks = 0; ks < 8; ks++) {
            uint32_t a0 = fu(B0[(mb + g)     * PN + 8 * ks + t]);
            uint32_t a1 = fu(B0[(mb + g + 8) * PN + 8 * ks + t]);
            uint32_t a2 = fu(B0[(mb + g)     * PN + 8 * ks + t + 4]);
            uint32_t a3 = fu(B0[(mb + g + 8) * PN + 8 * ks + t + 4]);
#pragma unroll
            for (int j = 0; j < 2; j++) {
                uint32_t b0 = fu(B0[(8 * ks + t)     * PN + nb + 8 * j + g]);
                uint32_t b1 = fu(B0[(8 * ks + t + 4) * PN + nb + 8 * j + g]);
                mma8(t1[j], a0, a1, a2, a3, b0, b1);
                mma8(t2[j], a0, a1, a2, a3, sfb[ks][j][0], sfb[ks][j][1]);
            }
        }
#pragma unroll
        for (int j = 0; j < 2; j++) {
            int c0 = nb + 8 * j + 2 * t;
            *(float2*)&B2[(mb + g)     * PN + c0] = make_float2(t1[j][0], t1[j][1]);
            *(float2*)&B2[(mb + g + 8) * PN + c0] = make_float2(t1[j][2], t1[j][3]);
            *(float2*)&B3[(mb + g)     * PN + c0] = make_float2(t2[j][0], t2[j][1]);
            *(float2*)&B3[(mb + g + 8) * PN + c0] = make_float2(t2[j][2], t2[j][3]);
        }
        __syncthreads();

        float u0[2][4], u1[2][4];
#pragma unroll
        for (int j = 0; j < 2; j++)
#pragma unroll
            for (int e = 0; e < 4; e++) { u0[j][e] = 0.f; u1[j][e] = 0.f; }
#pragma unroll
        for (int ks = 0; ks < 8; ks++) {
            uint32_t a0 = fu(B2[(mb + g)     * PN + 8 * ks + t]);
            uint32_t a1 = fu(B2[(mb + g + 8) * PN + 8 * ks + t]);
            uint32_t a2 = fu(B2[(mb + g)     * PN + 8 * ks + t + 4]);
            uint32_t a3 = fu(B2[(mb + g + 8) * PN + 8 * ks + t + 4]);
#pragma unroll
            for (int j = 0; j < 2; j++) {
                uint32_t b0 = fu(B3[(8 * ks + t)     * PN + nb + 8 * j + g]);
                uint32_t b1 = fu(B3[(8 * ks + t + 4) * PN + nb + 8 * j + g]);
                if (ks < 4) mma8(u0[j], a0, a1, a2, a3, b0, b1);
                else        mma8(u1[j], a0, a1, a2, a3, b0, b1);
            }
        }
#pragma unroll
        for (int j = 0; j < 2; j++) {
            int c0 = nb + 8 * j + 2 * t;
            float s0 = u0[j][0] + u1[j][0], s1 = u0[j][1] + u1[j][1];
            float s2 = u0[j][2] + u1[j][2], s3 = u0[j][3] + u1[j][3];
            float2 p0 = *(const float2*)&B0[(mb + g)     * PN + c0];
            float2 p1 = *(const float2*)&B0[(mb + g + 8) * PN + c0];
            *(float2*)&B0[(mb + g)     * PN + c0] =
                make_float2(1.5f * p0.x - 0.5f * s0, 1.5f * p0.y - 0.5f * s1);
            *(float2*)&B0[(mb + g + 8) * PN + c0] =
                make_float2(1.5f * p1.x - 0.5f * s2, 1.5f * p1.y - 0.5f * s3);
        }
        __syncthreads();
    }

    u64 acc[2][2], acc2[2][2];
    {
        mm_sym2(B0, B0, ib, jb, acc);
        mm_sym2(B0, B1, ib, jb, acc2);
#pragma unroll
        for (int ii = 0; ii < 2; ii++) {
            float2 l0 = unpk(acc[ii][0]);
            float2 l1 = unpk(acc[ii][1]);
            *(float4*)&B2[(ib + ii) * PN + jb] = make_float4(l0.x, l0.y, l1.x, l1.y);
            float2 m0 = unpk(acc2[ii][0]);
            float2 m1 = unpk(acc2[ii][1]);
            *(float4*)&B3[(ib + ii) * PN + jb] = make_float4(m0.x, m0.y, m1.x, m1.y);
        }
        __syncthreads();
        mm_sym2(B2, B3, ib, jb, acc);
#pragma unroll
        for (int ii = 0; ii < 2; ii++) {
            float2 l0 = unpk(acc[ii][0]);
            float2 l1 = unpk(acc[ii][1]);
            int base = (ib + ii) * PN + jb;
            float4 p = *(const float4*)&B0[base];
            *(float4*)&B0[base] = make_float4(1.5f * p.x - 0.5f * l0.x,
                                              1.5f * p.y - 0.5f * l0.y,
                                              1.5f * p.z - 0.5f * l1.x,
                                              1.5f * p.w - 0.5f * l1.y);
        }
        __syncthreads();
    }

#pragma unroll
    for (int ii = 0; ii < 2; ii++) {
        float4 p = *(const float4*)&B0[(ib + ii) * PN + jb];
        *(float4*)&d_wm[(ib + ii) * 64 + jb] =
            make_float4(p.x * srt, p.y * srt, p.z * srt, p.w * srt);
    }
    if (tid < 64) {
        float s = 0.f;
#pragma unroll 8
        for (int j = 0; j < 64; j++) s += B0[tid * PN + j] * (ssum[j] * inv_m);
        d_off[tid] = beta[tid] - srt * s;
    }
}

// ---------------------------------------------------------------------------
// Kernel 3: out = x + E@x + off. 2 warp-groups, each: 2 x-slots + 1 y-slot.
// Warp tile 32 rows x 32 cols.
// ---------------------------------------------------------------------------
__global__ __launch_bounds__(256, 2) void apply_kernel(
        const __grid_constant__ CUtensorMap tmX,
        const __grid_constant__ CUtensorMap tmO) {
    __shared__ float raw[6 * 4096 + 256];
    __shared__ float osh[64];
    __shared__ u64 mbar[4];
    float* base0 = (float*)(((uintptr_t)raw + 1023) & ~(uintptr_t)1023);

    int tid = threadIdx.x;
    int grp = tid >> 7, gt = tid & 127;
    int lane = gt & 31, gw = gt >> 5;
    int g = lane >> 2, t = lane & 3;
    int mb = (gw & 1) * 32, nb = (gw >> 1) * 32;
    int vc = blockIdx.x * 2 + grp;

    float* xg = base0 + grp * 3 * 4096;          // 2 x-slots + 1 y-slot
    float* yg = xg + 2 * 4096;
    uint32_t sb[2], mbr[2], yb;
#pragma unroll
    for (int i = 0; i < 2; i++) {
        sb[i]  = (uint32_t)__cvta_generic_to_shared(xg + i * 4096);
        mbr[i] = (uint32_t)__cvta_generic_to_shared(&mbar[grp * 2 + i]);
    }
    yb = (uint32_t)__cvta_generic_to_shared(yg);

    if (gt == 0) { mbar_init(mbr[0], 1); mbar_init(mbr[1], 1); }

    // resident E = wm - I fragments (32 rows/warp)
    uint32_t ea[2][8][4];
#pragma unroll
    for (int mi = 0; mi < 2; mi++) {
        int r0 = mb + 16 * mi + g, r1 = r0 + 8;
#pragma unroll
        for (int ks = 0; ks < 8; ks++) {
            int c0 = 8 * ks + t, c1 = c0 + 4;
            ea[mi][ks][0] = tf32r(d_wm[r0 * 64 + c0] - (r0 == c0 ? 1.f : 0.f));
            ea[mi][ks][1] = tf32r(d_wm[r1 * 64 + c0] - (r1 == c0 ? 1.f : 0.f));
            ea[mi][ks][2] = tf32r(d_wm[r0 * 64 + c1] - (r0 == c1 ? 1.f : 0.f));
            ea[mi][ks][3] = tf32r(d_wm[r1 * 64 + c1] - (r1 == c1 ? 1.f : 0.f));
        }
    }
    if (tid < 64) osh[tid] = d_off[tid];
    __syncthreads();

    float orow[2][2];
#pragma unroll
    for (int mi = 0; mi < 2; mi++) {
        orow[mi][0] = osh[mb + 16 * mi + g];
        orow[mi][1] = osh[mb + 16 * mi + g + 8];
    }

    if (gt == 0) load_chunk(sb[0], &tmX, vc, mbr[0]);

    int ph[2] = {0, 0};
    int it = 0;
    for (int ch = vc; ch < NCHUNK; ch += GRIDV, it++) {
        int s = it & 1;
        if (gt == 0) tma_wait<0>();         // previous y store complete
        mbar_wait(mbr[s], ph[s]); ph[s] ^= 1;
        gbar(grp + 1);

        int cn = ch + GRIDV;
        if (cn < NCHUNK && gt == 0)
            load_chunk(sb[s ^ 1], &tmX, cn, mbr[s ^ 1]);

        const float* xb = xg + s * 4096;

        float acc[2][4][4];
#pragma unroll
        for (int mi = 0; mi < 2; mi++) {
            int r0 = mb + 16 * mi + g, r1 = r0 + 8;
#pragma unroll
            for (int j = 0; j < 4; j++) {
                int cc = nb + 8 * j + 2 * t;
                float2 v0 = *(const float2*)&xb[swidx(r0, cc)];
                float2 v1 = *(const float2*)&xb[swidx(r1, cc)];
                acc[mi][j][0] = orow[mi][0] + v0.x;
                acc[mi][j][1] = orow[mi][0] + v0.y;
                acc[mi][j][2] = orow[mi][1] + v1.x;
                acc[mi][j][3] = orow[mi][1] + v1.y;
            }
        }

#pragma unroll
        for (int ks = 0; ks < 8; ks++) {
#pragma unroll
            for (int j = 0; j < 4; j++) {
                uint32_t b0 = fu(xb[swidx(8 * ks + t,     nb + 8 * j + g)]);
                uint32_t b1 = fu(xb[swidx(8 * ks + t + 4, nb + 8 * j + g)]);
#pragma unroll
                for (int mi = 0; mi < 2; mi++)
                    mma8(acc[mi][j], ea[mi][ks][0], ea[mi][ks][1],
                                     ea[mi][ks][2], ea[mi][ks][3], b0, b1);
            }
        }
#pragma unroll
        for (int mi = 0; mi < 2; mi++) {
            int r0 = mb + 16 * mi + g, r1 = r0 + 8;
#pragma unroll
            for (int j = 0; j < 4; j++) {
                int cc = nb + 8 * j + 2 * t;
                *(float2*)&yg[swidx(r0, cc)] = make_float2(acc[mi][j][0], acc[mi][j][1]);
                *(float2*)&yg[swidx(r1, cc)] = make_float2(acc[mi][j][2], acc[mi][j][3]);
            }
        }
        gbar(grp + 1);

        if (gt == 0) {
            fence_async();
            int b = ch / CPI, pc = (ch - b * CPI) * 64;
            tma_st(&tmO, pc,      0, b, yb);
            tma_st(&tmO, pc + 32, 0, b, yb + 8192);
            tma_commit();
        }
    }
    if (gt == 0) tma_wait<0>();
}

// ---------------------------------------------------------------------------
typedef CUresult (CUDAAPI *PFN_tmEnc)(CUtensorMap*, CUtensorMapDataType, cuuint32_t,
                                      void*, const cuuint64_t*, const cuuint64_t*,
                                      const cuuint32_t*, const cuuint32_t*,
                                      CUtensorMapInterleave, CUtensorMapSwizzle,
                                      CUtensorMapL2promotion, CUtensorMapFloatOOBfill);

extern "C" void kernel_launch(void* const* d_in, const int* in_sizes, int n_in,
                              void* d_out, int out_size) {
    (void)in_sizes; (void)n_in; (void)out_size;
    const float* X    = (const float*)d_in[0];
    const float* beta = (const float*)d_in[1];
    float* out        = (float*)d_out;

    PFN_tmEnc enc = nullptr;
    cudaDriverEntryPointQueryResult qr;
    cudaGetDriverEntryPoint("cuTensorMapEncodeTiled", (void**)&enc,
                            cudaEnableDefault, &qr);

    CUtensorMap tmX, tmO;
    cuuint64_t dims[3]    = {(cuuint64_t)HWP, (cuuint64_t)CCH, (cuuint64_t)NBATCH};
    cuuint64_t strides[2] = {(cuuint64_t)HWP * 4ull,
                             (cuuint64_t)CCH * (cuuint64_t)HWP * 4ull};
    cuuint32_t box[3] = {32u, 64u, 1u};
    cuuint32_t es[3]  = {1u, 1u, 1u};
    enc(&tmX, CU_TENSOR_MAP_DATA_TYPE_FLOAT32, 3, (void*)X, dims, strides, box, es,
        CU_TENSOR_MAP_INTERLEAVE_NONE, CU_TENSOR_MAP_SWIZZLE_128B,
        CU_TENSOR_MAP_L2_PROMOTION_L2_128B, CU_TENSOR_MAP_FLOAT_OOB_FILL_NONE);
    enc(&tmO, CU_TENSOR_MAP_DATA_TYPE_FLOAT32, 3, (void*)out, dims, strides, box, es,
        CU_TENSOR_MAP_INTERLEAVE_NONE, CU_TENSOR_MAP_SWIZZLE_128B,
        CU_TENSOR_MAP_L2_PROMOTION_L2_128B, CU_TENSOR_MAP_FLOAT_OOB_FILL_NONE);

    gram_kernel<<<GRIDB, 256>>>(tmX);
    reduce_kernel<<<264, 128>>>();
    ns_kernel<<<1, 512>>>(beta);
    apply_kernel<<<GRIDB, 256>>>(tmX, tmO);
}

// round 17
// speedup vs baseline: 1.5198x; 1.0683x over previous
#include <cuda_runtime.h>
#include <cuda.h>
#include <math.h>
#include <stdint.h>

#define CCH    64
#define HWP    3136
#define NBATCH 128
#define MTOT   401408
#define CPI    49
#define NCHUNK 6272
#define GRIDB  296
#define GRIDV  592          // virtual pipelines (2 per CTA)
#define PN     68
#define NS_TF  2            // tf32 iters after analytic P1 (P0 = 8I)
#define RCPG   74           // pipelines per reduce group (8*74=592)

typedef unsigned long long u64;

__device__ float d_gpart[GRIDV * 4096];
__device__ float d_spart[GRIDV * 64];
__device__ float d_qpart[GRIDV * 64];
__device__ float d_gram2[8 * 4096];
__device__ float d_sums2[8 * 64];
__device__ float d_qsum2[8 * 64];
__device__ float d_wm[4096];
__device__ float d_off[64];

// ---- swizzled tile indexing (TMA SW128, box 32x64 f32, halves at 0/8KB) ----
__device__ __forceinline__ int swidx(int c, int p) {
    return ((p >> 5) << 11) + (c << 5) + ((p & 31) ^ ((c & 7) << 2));
}

// ---- helpers ---------------------------------------------------------------
__device__ __forceinline__ uint32_t fu(float x) { return __float_as_uint(x); }
__device__ __forceinline__ uint32_t tf32r(float x) {
    uint32_t r; asm("cvt.rna.tf32.f32 %0, %1;" : "=r"(r) : "f"(x)); return r;
}
__device__ __forceinline__ void mma8(float c[4], uint32_t a0, uint32_t a1,
                                     uint32_t a2, uint32_t a3,
                                     uint32_t b0, uint32_t b1) {
    asm("mma.sync.aligned.m16n8k8.row.col.f32.tf32.tf32.f32 "
        "{%0,%1,%2,%3}, {%4,%5,%6,%7}, {%8,%9}, {%0,%1,%2,%3};"
        : "+f"(c[0]), "+f"(c[1]), "+f"(c[2]), "+f"(c[3])
        : "r"(a0), "r"(a1), "r"(a2), "r"(a3), "r"(b0), "r"(b1));
}
__device__ __forceinline__ void fma2(u64 &acc, u64 a, u64 b) {
    asm("fma.rn.f32x2 %0, %1, %2, %0;" : "+l"(acc) : "l"(a), "l"(b));
}
__device__ __forceinline__ u64 dup2(float x) {
    u64 r; asm("mov.b64 %0, {%1, %1};" : "=l"(r) : "r"(__float_as_uint(x))); return r;
}
__device__ __forceinline__ float2 unpk(u64 v) {
    float2 f; asm("mov.b64 {%0, %1}, %2;" : "=f"(f.x), "=f"(f.y) : "l"(v)); return f;
}
__device__ __forceinline__ void gbar(int id) {
    asm volatile("bar.sync %0, 128;" :: "r"(id) : "memory");
}
// ---- TMA machinery ---------------------------------------------------------
__device__ __forceinline__ void mbar_init(uint32_t mb, uint32_t cnt) {
    asm volatile("mbarrier.init.shared.b64 [%0], %1;" :: "r"(mb), "r"(cnt) : "memory");
}
__device__ __forceinline__ void mbar_expect(uint32_t mb, uint32_t bytes) {
    asm volatile("mbarrier.arrive.expect_tx.shared.b64 _, [%0], %1;"
                 :: "r"(mb), "r"(bytes) : "memory");
}
__device__ __forceinline__ void mbar_wait(uint32_t mb, uint32_t parity) {
    uint32_t done;
    do {
        asm volatile("{\n\t.reg .pred p;\n\t"
                     "mbarrier.try_wait.parity.acquire.cta.shared::cta.b64 p, [%1], %2, 0x989680;\n\t"
                     "selp.b32 %0, 1, 0, p;\n\t}"
                     : "=r"(done) : "r"(mb), "r"(parity) : "memory");
    } while (!done);
}
__device__ __forceinline__ void tma_ld(uint32_t dst, const CUtensorMap* tm,
                                       int x, int y, int z, uint32_t mb) {
    asm volatile("cp.async.bulk.tensor.3d.shared::cta.global.tile.mbarrier::complete_tx::bytes "
                 "[%0], [%1, {%2, %3, %4}], [%5];"
                 :: "r"(dst), "l"(tm), "r"(x), "r"(y), "r"(z), "r"(mb) : "memory");
}
__device__ __forceinline__ void tma_st(const CUtensorMap* tm, int x, int y, int z,
                                       uint32_t src) {
    asm volatile("cp.async.bulk.tensor.3d.global.shared::cta.tile.bulk_group "
                 "[%0, {%1, %2, %3}], [%4];"
                 :: "l"(tm), "r"(x), "r"(y), "r"(z), "r"(src) : "memory");
}
__device__ __forceinline__ void tma_commit() {
    asm volatile("cp.async.bulk.commit_group;" ::: "memory");
}
template<int N> __device__ __forceinline__ void tma_wait() {
    asm volatile("cp.async.bulk.wait_group %0;" :: "n"(N) : "memory");
}
__device__ __forceinline__ void fence_async() {
    asm volatile("fence.proxy.async;" ::: "memory");
}
__device__ __forceinline__ void load_chunk(uint32_t dst, const CUtensorMap* tm,
                                           int ch, uint32_t mb) {
    int b = ch / CPI, pc = (ch - b * CPI) * 64;
    mbar_expect(mb, 16384u);
    tma_ld(dst,        tm, pc,      0, b, mb);
    tma_ld(dst + 8192, tm, pc + 32, 0, b, mb);
}

// ---------------------------------------------------------------------------
// Kernel 1: Gram. 2 warp-groups, each an independent TMA+mma pipeline.
// ---------------------------------------------------------------------------
__global__ __launch_bounds__(256, 2) void gram_kernel(const __grid_constant__ CUtensorMap tmX) {
    __shared__ float raw_x[6 * 4096 + 256];
    __shared__ u64 mbar[6];
    float* xb0 = (float*)(((uintptr_t)raw_x + 1023) & ~(uintptr_t)1023);

    int tid = threadIdx.x;
    int grp = tid >> 7, gt = tid & 127;
    int lane = gt & 31, gw = gt >> 5;
    int g = lane >> 2, t = lane & 3;
    int mb = gw * 16;
    int sc = gt >> 1, st = gt & 1;
    int vc = blockIdx.x * 2 + grp;

    float* xg = xb0 + grp * 3 * 4096;
    uint32_t sb[3], mbr[3];
#pragma unroll
    for (int i = 0; i < 3; i++) {
        sb[i]  = (uint32_t)__cvta_generic_to_shared(xg + i * 4096);
        mbr[i] = (uint32_t)__cvta_generic_to_shared(&mbar[grp * 3 + i]);
    }
    if (gt == 0) { mbar_init(mbr[0], 1); mbar_init(mbr[1], 1); mbar_init(mbr[2], 1); }
    __syncthreads();

    float acc[8][4];
#pragma unroll
    for (int j = 0; j < 8; j++)
#pragma unroll
        for (int e = 0; e < 4; e++) acc[j][e] = 0.f;
    float csum = 0.f, cq = 0.f;

    if (gt == 0) {
#pragma unroll
        for (int p = 0; p < 2; p++)
            load_chunk(sb[p], &tmX, vc + p * GRIDV, mbr[p]);
    }

    int ph[3] = {0, 0, 0};
    int it = 0;
    for (int ch = vc; ch < NCHUNK; ch += GRIDV, it++) {
        int s = it % 3;
        mbar_wait(mbr[s], ph[s]); ph[s] ^= 1;
        gbar(grp + 1);

        int cn = ch + 2 * GRIDV;
        if (cn < NCHUNK && gt == 0) {
            int sn = (it + 2) % 3;
            load_chunk(sb[sn], &tmX, cn, mbr[sn]);
        }

        const float* xb = xg + s * 4096;

        {
            float sv = 0.f, q2 = 0.f;
#pragma unroll
            for (int qq = 0; qq < 8; qq++) {
                float4 v = *(const float4*)&xb[swidx(sc, (st * 8 + qq) * 4)];
                sv += (v.x + v.y) + (v.z + v.w);
                q2 += v.x * v.x + v.y * v.y + v.z * v.z + v.w * v.w;
            }
            csum += sv; cq += q2;
        }

#pragma unroll
        for (int kg = 0; kg < 2; kg++) {
            int kb = kg * 32;
            float4 Al  = *(const float4*)&xb[swidx(mb + g,     kb + 4 * t)];
            float4 Ah  = *(const float4*)&xb[swidx(mb + g,     kb + 16 + 4 * t)];
            float4 A2l = *(const float4*)&xb[swidx(mb + g + 8, kb + 4 * t)];
            float4 A2h = *(const float4*)&xb[swidx(mb + g + 8, kb + 16 + 4 * t)];
#pragma unroll
            for (int j = 0; j < 8; j++) {
                float4 Bl = *(const float4*)&xb[swidx(8 * j + g, kb + 4 * t)];
                float4 Bh = *(const float4*)&xb[swidx(8 * j + g, kb + 16 + 4 * t)];
                mma8(acc[j], fu(Al.x), fu(A2l.x), fu(Ah.x), fu(A2h.x), fu(Bl.x), fu(Bh.x));
                mma8(acc[j], fu(Al.y), fu(A2l.y), fu(Ah.y), fu(A2h.y), fu(Bl.y), fu(Bh.y));
                mma8(acc[j], fu(Al.z), fu(A2l.z), fu(Ah.z), fu(A2h.z), fu(Bl.z), fu(Bh.z));
                mma8(acc[j], fu(Al.w), fu(A2l.w), fu(Ah.w), fu(A2h.w), fu(Bl.w), fu(Bh.w));
            }
        }
    }

    float* gp = &d_gpart[vc * 4096];
#pragma unroll
    for (int j = 0; j < 8; j++) {
        int col = 8 * j + 2 * t;
        gp[(mb + g)     * 64 + col]     = acc[j][0];
        gp[(mb + g)     * 64 + col + 1] = acc[j][1];
        gp[(mb + g + 8) * 64 + col]     = acc[j][2];
        gp[(mb + g + 8) * 64 + col + 1] = acc[j][3];
    }
    csum += __shfl_xor_sync(0xffffffffu, csum, 1);
    cq   += __shfl_xor_sync(0xffffffffu, cq, 1);
    if (st == 0) {
        d_spart[vc * 64 + sc] = csum;
        d_qpart[vc * 64 + sc] = cq;
    }
}

// ---------------------------------------------------------------------------
// Kernel 1b: reduce — 8 groups x 74 pipelines, partial outputs.
// ---------------------------------------------------------------------------
__global__ __launch_bounds__(128) void reduce_kernel() {
    int grp = blockIdx.x / 33;
    int blk = blockIdx.x - grp * 33;
    int idx = blk * 128 + threadIdx.x;
    int c0 = grp * RCPG;
    if (idx < 4096) {
        float s = 0.f;
#pragma unroll 4
        for (int c = 0; c < RCPG; c++) s += d_gpart[(c0 + c) * 4096 + idx];
        d_gram2[grp * 4096 + idx] = s;
    } else if (idx < 4160) {
        int j = idx - 4096;
        float s = 0.f;
#pragma unroll 4
        for (int c = 0; c < RCPG; c++) s += d_spart[(c0 + c) * 64 + j];
        d_sums2[grp * 64 + j] = s;
    } else if (idx < 4224) {
        int j = idx - 4160;
        float s = 0.f;
#pragma unroll 4
        for (int c = 0; c < RCPG; c++) s += d_qpart[(c0 + c) * 64 + j];
        d_qsum2[grp * 64 + j] = s;
    }
}

// ---------------------------------------------------------------------------
// Kernel 2: Sigma + Newton-Schulz with spectral init P0 = 8I.
// P1 = 12I - 256 Sigma_N (analytic), NS_TF=2 tf32 2-stage iters, 1 exact.
// ---------------------------------------------------------------------------
__device__ __forceinline__ void mm_sym2(const float* __restrict__ A,
                                        const float* __restrict__ Bm,
                                        int ib, int jb, u64 acc[2][2]) {
#pragma unroll
    for (int ii = 0; ii < 2; ii++) { acc[ii][0] = 0ull; acc[ii][1] = 0ull; }
#pragma unroll 8
    for (int k = 0; k < 64; k++) {
        float2 a = *(const float2*)&A[k * PN + ib];
        ulonglong2 bv = *(const ulonglong2*)&Bm[k * PN + jb];
        u64 d0 = dup2(a.x), d1 = dup2(a.y);
        fma2(acc[0][0], d0, bv.x); fma2(acc[0][1], d0, bv.y);
        fma2(acc[1][0], d1, bv.x); fma2(acc[1][1], d1, bv.y);
    }
}

__global__ __launch_bounds__(512) void ns_kernel(const float* __restrict__ beta) {
    __shared__ __align__(16) float B0[64 * PN];
    __shared__ __align__(16) float B1[64 * PN];
    __shared__ __align__(16) float B2[64 * PN];
    __shared__ __align__(16) float B3[64 * PN];
    __shared__ float ssum[64], sq[64];
    int tid = threadIdx.x, lane = tid & 31, w = tid >> 5;
    int g = lane >> 2, t = lane & 3;
    int mb = (w & 3) * 16, nb = (w >> 2) * 16;
    int ib = (tid >> 4) * 2, jb = (tid & 15) * 4;
    const float inv_m = 1.f / (float)MTOT;

    if (tid < 64) {
        float s = 0.f, q = 0.f;
#pragma unroll
        for (int r = 0; r < 8; r++) {
            s += d_sums2[r * 64 + tid];
            q += d_qsum2[r * 64 + tid];
        }
        ssum[tid] = s; sq[tid] = q;
    }
    __syncthreads();

    for (int idx = tid; idx < 4096; idx += 512) {
        int i = idx >> 6, j = idx & 63;
        float gsum = 0.f;
#pragma unroll
        for (int r = 0; r < 8; r++) gsum += d_gram2[r * 4096 + idx];
        float mi = ssum[i] * inv_m, mj = ssum[j] * inv_m;
        float s;
        if (i == j) s = sq[i] * inv_m - mi * mi + 1e-5f;
        else        s = (gsum * inv_m - mi * mj) * 0.9f;
        B1[i * PN + j] = s;
    }
    __syncthreads();

    if (tid < 32) {
        float s = B1[tid * PN + tid] + B1[(tid + 32) * PN + (tid + 32)];
#pragma unroll
        for (int o = 16; o > 0; o >>= 1) s += __shfl_xor_sync(0xffffffffu, s, o);
        if (tid == 0) B2[0] = s;
    }
    __syncthreads();
    float rTr = 1.f / B2[0];
    float srt = sqrtf(rTr);
    __syncthreads();

    // Sigma_N; spectral init: P0 = 8I (mean eigenvalue of Sigma_N = 1/64 exactly)
    // -> P1 = 1.5*8I - 0.5*512*Sigma_N = 12I - 256*Sigma_N (analytic)
    for (int idx = tid; idx < 4096; idx += 512) {
        int i = idx >> 6, j = idx & 63;
        float sn = B1[i * PN + j] * rTr;
        B1[i * PN + j] = sn;
        B0[i * PN + j] = (i == j ? 12.f : 0.f) - 256.f * sn;
    }
    __syncthreads();

    uint32_t sfb[8][2][2];
#pragma unroll
    for (int ks = 0; ks < 8; ks++)
#pragma unroll
        for (int j = 0; j < 2; j++) {
            sfb[ks][j][0] = fu(B1[(8 * ks + t)     * PN + nb + 8 * j + g]);
            sfb[ks][j][1] = fu(B1[(8 * ks + t + 4) * PN + nb + 8 * j + g]);
        }

    for (int it = 0; it < NS_TF; it++) {
        float t1[2][4], t2[2][4];
#pragma unroll
        for (int j = 0; j < 2; j++)
#pragma unroll
            for (int e = 0; e < 4; e++) { t1[j][e] = 0.f; t2[j][e] = 0.f; }
#pragma unroll
        for (int ks = 0; ks < 8; ks++) {
            uint32_t a0 = fu(B0[(mb + g)     * PN + 8 * ks + t]);
            uint32_t a1 = fu(B0[(mb + g + 8) * PN + 8 * ks + t]);
            uint32_t a2 = fu(B0[(mb + g)     * PN + 8 * ks + t + 4]);
            uint32_t a3 = fu(B0[(mb + g + 8) * PN + 8 * ks + t + 4]);
#pragma unroll
            for (int j = 0; j < 2; j++) {
                uint32_t b0 = fu(B0[(8 * ks + t)     * PN + nb + 8 * j + g]);
                uint32_t b1 = fu(B0[(8 * ks + t + 4) * PN + nb + 8 * j + g]);
                mma8(t1[j], a0, a1, a2, a3, b0, b1);
                mma8(t2[j], a0, a1, a2, a3, sfb[ks][j][0], sfb[ks][j][1]);
            }
        }
#pragma unroll
        for (int j = 0; j < 2; j++) {
            int c0 = nb + 8 * j + 2 * t;
            *(float2*)&B2[(mb + g)     * PN + c0] = make_float2(t1[j][0], t1[j][1]);
            *(float2*)&B2[(mb + g + 8) * PN + c0] = make_float2(t1[j][2], t1[j][3]);
            *(float2*)&B3[(mb + g)     * PN + c0] = make_float2(t2[j][0], t2[j][1]);
            *(float2*)&B3[(mb + g + 8) * PN + c0] = make_float2(t2[j][2], t2[j][3]);
        }
        __syncthreads();

        float u0[2][4], u1[2][4];
#pragma unroll
        for (int j = 0; j < 2; j++)
#pragma unroll
            for (int e = 0; e < 4; e++) { u0[j][e] = 0.f; u1[j][e] = 0.f; }
#pragma unroll
        for (int ks = 0; ks < 8; ks++) {
            uint32_t a0 = fu(B2[(mb + g)     * PN + 8 * ks + t]);
            uint32_t a1 = fu(B2[(mb + g + 8) * PN + 8 * ks + t]);
            uint32_t a2 = fu(B2[(mb + g)     * PN + 8 * ks + t + 4]);
            uint32_t a3 = fu(B2[(mb + g + 8) * PN + 8 * ks + t + 4]);
#pragma unroll
            for (int j = 0; j < 2; j++) {
                uint32_t b0 = fu(B3[(8 * ks + t)     * PN + nb + 8 * j + g]);
                uint32_t b1 = fu(B3[(8 * ks + t + 4) * PN + nb + 8 * j + g]);
                if (ks < 4) mma8(u0[j], a0, a1, a2, a3, b0, b1);
                else        mma8(u1[j], a0, a1, a2, a3, b0, b1);
            }
        }
#pragma unroll
        for (int j = 0; j < 2; j++) {
            int c0 = nb + 8 * j + 2 * t;
            float s0 = u0[j][0] + u1[j][0], s1 = u0[j][1] + u1[j][1];
            float s2 = u0[j][2] + u1[j][2], s3 = u0[j][3] + u1[j][3];
            float2 p0 = *(const float2*)&B0[(mb + g)     * PN + c0];
            float2 p1 = *(const float2*)&B0[(mb + g + 8) * PN + c0];
            *(float2*)&B0[(mb + g)     * PN + c0] =
                make_float2(1.5f * p0.x - 0.5f * s0, 1.5f * p0.y - 0.5f * s1);
            *(float2*)&B0[(mb + g + 8) * PN + c0] =
                make_float2(1.5f * p1.x - 0.5f * s2, 1.5f * p1.y - 0.5f * s3);
        }
        __syncthreads();
    }

    // exact fp32 final iteration (contracts tf32 noise quadratically)
    u64 acc[2][2], acc2[2][2];
    {
        mm_sym2(B0, B0, ib, jb, acc);
        mm_sym2(B0, B1, ib, jb, acc2);
#pragma unroll
        for (int ii = 0; ii < 2; ii++) {
            float2 l0 = unpk(acc[ii][0]);
            float2 l1 = unpk(acc[ii][1]);
            *(float4*)&B2[(ib + ii) * PN + jb] = make_float4(l0.x, l0.y, l1.x, l1.y);
            float2 m0 = unpk(acc2[ii][0]);
            float2 m1 = unpk(acc2[ii][1]);
            *(float4*)&B3[(ib + ii) * PN + jb] = make_float4(m0.x, m0.y, m1.x, m1.y);
        }
        __syncthreads();
        mm_sym2(B2, B3, ib, jb, acc);
#pragma unroll
        for (int ii = 0; ii < 2; ii++) {
            float2 l0 = unpk(acc[ii][0]);
            float2 l1 = unpk(acc[ii][1]);
            int base = (ib + ii) * PN + jb;
            float4 p = *(const float4*)&B0[base];
            *(float4*)&B0[base] = make_float4(1.5f * p.x - 0.5f * l0.x,
                                              1.5f * p.y - 0.5f * l0.y,
                                              1.5f * p.z - 0.5f * l1.x,
                                              1.5f * p.w - 0.5f * l1.y);
        }
        __syncthreads();
    }

#pragma unroll
    for (int ii = 0; ii < 2; ii++) {
        float4 p = *(const float4*)&B0[(ib + ii) * PN + jb];
        *(float4*)&d_wm[(ib + ii) * 64 + jb] =
            make_float4(p.x * srt, p.y * srt, p.z * srt, p.w * srt);
    }
    if (tid < 64) {
        float s = 0.f;
#pragma unroll 8
        for (int j = 0; j < 64; j++) s += B0[tid * PN + j] * (ssum[j] * inv_m);
        d_off[tid] = beta[tid] - srt * s;
    }
}

// ---------------------------------------------------------------------------
// Kernel 3: out = x + E@x + off. 2 warp-groups, each: 2 x-slots + 1 y-slot.
// ---------------------------------------------------------------------------
__global__ __launch_bounds__(256, 2) void apply_kernel(
        const __grid_constant__ CUtensorMap tmX,
        const __grid_constant__ CUtensorMap tmO) {
    __shared__ float raw[6 * 4096 + 256];
    __shared__ float osh[64];
    __shared__ u64 mbar[4];
    float* base0 = (float*)(((uintptr_t)raw + 1023) & ~(uintptr_t)1023);

    int tid = threadIdx.x;
    int grp = tid >> 7, gt = tid & 127;
    int lane = gt & 31, gw = gt >> 5;
    int g = lane >> 2, t = lane & 3;
    int mb = (gw & 1) * 32, nb = (gw >> 1) * 32;
    int vc = blockIdx.x * 2 + grp;

    float* xg = base0 + grp * 3 * 4096;
    float* yg = xg + 2 * 4096;
    uint32_t sb[2], mbr[2], yb;
#pragma unroll
    for (int i = 0; i < 2; i++) {
        sb[i]  = (uint32_t)__cvta_generic_to_shared(xg + i * 4096);
        mbr[i] = (uint32_t)__cvta_generic_to_shared(&mbar[grp * 2 + i]);
    }
    yb = (uint32_t)__cvta_generic_to_shared(yg);

    if (gt == 0) { mbar_init(mbr[0], 1); mbar_init(mbr[1], 1); }

    uint32_t ea[2][8][4];
#pragma unroll
    for (int mi = 0; mi < 2; mi++) {
        int r0 = mb + 16 * mi + g, r1 = r0 + 8;
#pragma unroll
        for (int ks = 0; ks < 8; ks++) {
            int c0 = 8 * ks + t, c1 = c0 + 4;
            ea[mi][ks][0] = tf32r(d_wm[r0 * 64 + c0] - (r0 == c0 ? 1.f : 0.f));
            ea[mi][ks][1] = tf32r(d_wm[r1 * 64 + c0] - (r1 == c0 ? 1.f : 0.f));
            ea[mi][ks][2] = tf32r(d_wm[r0 * 64 + c1] - (r0 == c1 ? 1.f : 0.f));
            ea[mi][ks][3] = tf32r(d_wm[r1 * 64 + c1] - (r1 == c1 ? 1.f : 0.f));
        }
    }
    if (tid < 64) osh[tid] = d_off[tid];
    __syncthreads();

    float orow[2][2];
#pragma unroll
    for (int mi = 0; mi < 2; mi++) {
        orow[mi][0] = osh[mb + 16 * mi + g];
        orow[mi][1] = osh[mb + 16 * mi + g + 8];
    }

    if (gt == 0) load_chunk(sb[0], &tmX, vc, mbr[0]);

    int ph[2] = {0, 0};
    int it = 0;
    for (int ch = vc; ch < NCHUNK; ch += GRIDV, it++) {
        int s = it & 1;
        if (gt == 0) tma_wait<0>();
        mbar_wait(mbr[s], ph[s]); ph[s] ^= 1;
        gbar(grp + 1);

        int cn = ch + GRIDV;
        if (cn < NCHUNK && gt == 0)
            load_chunk(sb[s ^ 1], &tmX, cn, mbr[s ^ 1]);

        const float* xb = xg + s * 4096;

        float acc[2][4][4];
#pragma unroll
        for (int mi = 0; mi < 2; mi++) {
            int r0 = mb + 16 * mi + g, r1 = r0 + 8;
#pragma unroll
            for (int j = 0; j < 4; j++) {
                int cc = nb + 8 * j + 2 * t;
                float2 v0 = *(const float2*)&xb[swidx(r0, cc)];
                float2 v1 = *(const float2*)&xb[swidx(r1, cc)];
                acc[mi][j][0] = orow[mi][0] + v0.x;
                acc[mi][j][1] = orow[mi][0] + v0.y;
                acc[mi][j][2] = orow[mi][1] + v1.x;
                acc[mi][j][3] = orow[mi][1] + v1.y;
            }
        }

#pragma unroll
        for (int ks = 0; ks < 8; ks++) {
#pragma unroll
            for (int j = 0; j < 4; j++) {
                uint32_t b0 = fu(xb[swidx(8 * ks + t,     nb + 8 * j + g)]);
                uint32_t b1 = fu(xb[swidx(8 * ks + t + 4, nb + 8 * j + g)]);
#pragma unroll
                for (int mi = 0; mi < 2; mi++)
                    mma8(acc[mi][j], ea[mi][ks][0], ea[mi][ks][1],
                                     ea[mi][ks][2], ea[mi][ks][3], b0, b1);
            }
        }
#pragma unroll
        for (int mi = 0; mi < 2; mi++) {
            int r0 = mb + 16 * mi + g, r1 = r0 + 8;
#pragma unroll
            for (int j = 0; j < 4; j++) {
                int cc = nb + 8 * j + 2 * t;
                *(float2*)&yg[swidx(r0, cc)] = make_float2(acc[mi][j][0], acc[mi][j][1]);
                *(float2*)&yg[swidx(r1, cc)] = make_float2(acc[mi][j][2], acc[mi][j][3]);
            }
        }
        gbar(grp + 1);

        if (gt == 0) {
            fence_async();
            int b = ch / CPI, pc = (ch - b * CPI) * 64;
            tma_st(&tmO, pc,      0, b, yb);
            tma_st(&tmO, pc + 32, 0, b, yb + 8192);
            tma_commit();
        }
    }
    if (gt == 0) tma_wait<0>();
}

// ---------------------------------------------------------------------------
typedef CUresult (CUDAAPI *PFN_tmEnc)(CUtensorMap*, CUtensorMapDataType, cuuint32_t,
                                      void*, const cuuint64_t*, const cuuint64_t*,
                                      const cuuint32_t*, const cuuint32_t*,
                                      CUtensorMapInterleave, CUtensorMapSwizzle,
                                      CUtensorMapL2promotion, CUtensorMapFloatOOBfill);

extern "C" void kernel_launch(void* const* d_in, const int* in_sizes, int n_in,
                              void* d_out, int out_size) {
    (void)in_sizes; (void)n_in; (void)out_size;
    const float* X    = (const float*)d_in[0];
    const float* beta = (const float*)d_in[1];
    float* out        = (float*)d_out;

    PFN_tmEnc enc = nullptr;
    cudaDriverEntryPointQueryResult qr;
    cudaGetDriverEntryPoint("cuTensorMapEncodeTiled", (void**)&enc,
                            cudaEnableDefault, &qr);

    CUtensorMap tmX, tmO;
    cuuint64_t dims[3]    = {(cuuint64_t)HWP, (cuuint64_t)CCH, (cuuint64_t)NBATCH};
    cuuint64_t strides[2] = {(cuuint64_t)HWP * 4ull,
                             (cuuint64_t)CCH * (cuuint64_t)HWP * 4ull};
    cuuint32_t box[3] = {32u, 64u, 1u};
    cuuint32_t es[3]  = {1u, 1u, 1u};
    enc(&tmX, CU_TENSOR_MAP_DATA_TYPE_FLOAT32, 3, (void*)X, dims, strides, box, es,
        CU_TENSOR_MAP_INTERLEAVE_NONE, CU_TENSOR_MAP_SWIZZLE_128B,
        CU_TENSOR_MAP_L2_PROMOTION_L2_128B, CU_TENSOR_MAP_FLOAT_OOB_FILL_NONE);
    enc(&tmO, CU_TENSOR_MAP_DATA_TYPE_FLOAT32, 3, (void*)out, dims, strides, box, es,
        CU_TENSOR_MAP_INTERLEAVE_NONE, CU_TENSOR_MAP_SWIZZLE_128B,
        CU_TENSOR_MAP_L2_PROMOTION_L2_128B, CU_TENSOR_MAP_FLOAT_OOB_FILL_NONE);

    gram_kernel<<<GRIDB, 256>>>(tmX);
    reduce_kernel<<<264, 128>>>();
    ns_kernel<<<1, 512>>>(beta);
    apply_kernel<<<GRIDB, 256>>>(tmX, tmO);
}